// round 6
// baseline (speedup 1.0000x reference)
#include <cuda_runtime.h>
#include <cstddef>
#include <cstdint>

// Problem constants
#define S_LEN   2048
#define BATCH   2
#define DMODEL  1024
#define NHEAD   16
#define DHEAD   64
#define FFN_DIM 4096
#define NEXP    8
#define NTOK    (S_LEN*BATCH)          // 4096 tokens, t = s*BATCH + b

// ---------------- scratch (static device globals; no runtime allocation) ----
__device__ float g_ln1 [(size_t)NTOK*DMODEL];
__device__ float g_qkv [(size_t)NTOK*3*DMODEL];
__device__ float g_attn[(size_t)NTOK*DMODEL];
__device__ float g_x2  [(size_t)NTOK*DMODEL];
__device__ float g_ln2 [(size_t)NTOK*DMODEL];
__device__ float g_h1  [(size_t)NEXP*NTOK*FFN_DIM];   // expert hidden
__device__ float g_y   [(size_t)NEXP*NTOK*DMODEL];    // expert outputs
__device__ int   g_rows[NEXP*NTOK];
__device__ float g_rwgt[NEXP*NTOK];
__device__ int   g_trow[2*NTOK];
__device__ int   g_cnt [NEXP];

// ---------------- helpers ----------------------------------------------------
__device__ __forceinline__ uint32_t smem_u32(const void* p) {
    return (uint32_t)__cvta_generic_to_shared(p);
}
#define CP_ASYNC16(dst, src) \
    asm volatile("cp.async.cg.shared.global [%0], [%1], 16;\n" :: "r"(dst), "l"(src))
#define CP_COMMIT()  asm volatile("cp.async.commit_group;\n")
#define CP_WAIT1()   asm volatile("cp.async.wait_group 1;\n")

__device__ __forceinline__ void mma_tf32(float c[4], const uint32_t a[4], const uint32_t b[2]) {
    asm volatile(
        "mma.sync.aligned.m16n8k8.row.col.f32.tf32.tf32.f32 "
        "{%0,%1,%2,%3}, {%4,%5,%6,%7}, {%8,%9}, {%0,%1,%2,%3};"
        : "+f"(c[0]), "+f"(c[1]), "+f"(c[2]), "+f"(c[3])
        : "r"(a[0]), "r"(a[1]), "r"(a[2]), "r"(a[3]), "r"(b[0]), "r"(b[1]));
}

// packed fp32x2 (Blackwell FFMA2 — baseline sm_100-family PTX, no 'a' needed)
typedef unsigned long long ull_t;
#define FMA2(d, a, b) \
    asm("fma.rn.f32x2 %0, %1, %2, %0;" : "+l"(d) : "l"(a), "l"(b))
#define ADD2(d, a, b) \
    asm("add.rn.f32x2 %0, %1, %2;" : "=l"(d) : "l"(a), "l"(b))
#define MUL2(d, a, b) \
    asm("mul.rn.f32x2 %0, %1, %2;" : "=l"(d) : "l"(a), "l"(b))
__device__ __forceinline__ ull_t pk2(float lo, float hi) {
    ull_t r; asm("mov.b64 %0, {%1, %2};" : "=l"(r) : "f"(lo), "f"(hi)); return r;
}
__device__ __forceinline__ void upk2(float& lo, float& hi, ull_t v) {
    asm("mov.b64 {%0, %1}, %2;" : "=f"(lo), "=f"(hi) : "l"(v));
}

// ---------------- LayerNorm: one block per token row --------------------------
__global__ __launch_bounds__(256) void ln_kernel(
    const float* __restrict__ x, const float* __restrict__ g,
    const float* __restrict__ b, float* __restrict__ y)
{
    const int t   = blockIdx.x;
    const int tid = threadIdx.x;
    const float* xr = x + (size_t)t * DMODEL;
    float4 v = *(const float4*)(xr + tid * 4);
    float s  = v.x + v.y + v.z + v.w;
    float s2 = v.x*v.x + v.y*v.y + v.z*v.z + v.w*v.w;
    __shared__ float red[64];
    const int lane = tid & 31, wid = tid >> 5;
    #pragma unroll
    for (int off = 16; off; off >>= 1) {
        s  += __shfl_down_sync(0xffffffffu, s,  off);
        s2 += __shfl_down_sync(0xffffffffu, s2, off);
    }
    if (lane == 0) { red[wid] = s; red[32 + wid] = s2; }
    __syncthreads();
    if (tid == 0) {
        float ts = 0.f, ts2 = 0.f;
        #pragma unroll
        for (int i = 0; i < 8; i++) { ts += red[i]; ts2 += red[32 + i]; }
        float mean = ts * (1.f / DMODEL);
        float var  = ts2 * (1.f / DMODEL) - mean * mean;
        red[16] = mean;
        red[17] = rsqrtf(var + 1e-5f);
    }
    __syncthreads();
    const float mean = red[16], rstd = red[17];
    float4 gg = *(const float4*)(g + tid * 4);
    float4 bb = *(const float4*)(b + tid * 4);
    float4 o;
    o.x = (v.x - mean) * rstd * gg.x + bb.x;
    o.y = (v.y - mean) * rstd * gg.y + bb.y;
    o.z = (v.z - mean) * rstd * gg.z + bb.z;
    o.w = (v.w - mean) * rstd * gg.w + bb.w;
    *(float4*)(y + (size_t)t * DMODEL + tid * 4) = o;
}

// ---------------- TF32 tensor-core GEMM (128x256 tile, 64x64 warp tiles) ------
// C[m,n] = sum_k A[m,k] * B[n,k]  (row-major A, row-major B as [N][K])
// BK=16, 3-stage cp.async pipeline, 256 threads = 8 warps (2m x 4n),
// each warp 64x64 via m16n8k8 tf32 (4 m-frags x 8 n-frags x 2 k-steps).
// smem: [row][20] layout -> all fragment LDS conflict-free.
// EPI: 0 plain, 1 +bias, 2 +bias+res, 3 silu(other)*acc, 4 rowscale*acc
#define A_STAGE_F  (128 * 20)            // 2560 floats
#define B_STAGE_F  (256 * 20)            // 5120 floats
#define GEMM_SMEM  (3 * (A_STAGE_F + B_STAGE_F) * 4)   // 92160 B

template<int EPI, bool GATHER, bool GROUPED>
__global__ __launch_bounds__(256) void gemm_tf32(
    const float* __restrict__ A, const float* __restrict__ Bw, float* __restrict__ C,
    const float* __restrict__ bias, const float* __restrict__ res,
    const float* __restrict__ other, const float* __restrict__ rowscale,
    const int* __restrict__ rowsIdx, const int* __restrict__ cnt,
    int M, int N, int K,
    size_t strideAe, size_t strideBe, size_t strideCe)
{
    const int e  = GROUPED ? blockIdx.z : 0;
    int Me = M;
    if (GROUPED && cnt) Me = cnt[e];
    const int m0 = blockIdx.y * 128;
    if (m0 >= Me) return;
    const int n0 = blockIdx.x * 256;

    const float* Ae = A  + (size_t)e * strideAe;
    const float* Be = Bw + (size_t)e * strideBe;
    float*       Ce = C  + (size_t)e * strideCe;

    extern __shared__ float sh[];
    float* Asm = sh;                             // [3][128][20]
    float* Bsm = sh + 3 * A_STAGE_F;             // [3][256][20]

    const int tid  = threadIdx.x;
    const int lane = tid & 31, wid = tid >> 5;
    const int wm = wid >> 2, wn = wid & 3;       // warp grid 2 x 4
    const int q  = lane >> 2, r = lane & 3;

    // ---- staging: thread owns 2 A-rows + 4 B-rows, one 16B chunk each
    const int ldRow = tid >> 2;                  // 0..63
    const int c4    = (tid & 3) << 2;            // float offset 0,4,8,12
    int amr0 = m0 + ldRow, amr1 = m0 + 64 + ldRow;
    if (amr0 >= Me) amr0 = Me - 1;
    if (amr1 >= Me) amr1 = Me - 1;
    size_t ar0, ar1;
    if (GATHER) {
        ar0 = (size_t)rowsIdx[e * NTOK + amr0];
        ar1 = (size_t)rowsIdx[e * NTOK + amr1];
    } else {
        ar0 = (size_t)amr0; ar1 = (size_t)amr1;
    }
    const float* aSrc0 = Ae + ar0 * K + c4;
    const float* aSrc1 = Ae + ar1 * K + c4;
    const float* bSrc0 = Be + (size_t)(n0 + ldRow      ) * K + c4;
    const float* bSrc1 = Be + (size_t)(n0 + ldRow +  64) * K + c4;
    const float* bSrc2 = Be + (size_t)(n0 + ldRow + 128) * K + c4;
    const float* bSrc3 = Be + (size_t)(n0 + ldRow + 192) * K + c4;

    const uint32_t aStB = A_STAGE_F * 4, bStB = B_STAGE_F * 4;
    const uint32_t sA0 = smem_u32(Asm) + (uint32_t)(ldRow * 20 + c4) * 4;
    const uint32_t sA1 = sA0 + 64 * 20 * 4;
    const uint32_t sB0 = smem_u32(Bsm) + (uint32_t)(ldRow * 20 + c4) * 4;
    const uint32_t sB1 = sB0 +  64 * 20 * 4;
    const uint32_t sB2 = sB0 + 128 * 20 * 4;
    const uint32_t sB3 = sB0 + 192 * 20 * 4;

    const int KT = K >> 4;

    // prefetch stages 0,1
    #pragma unroll
    for (int s = 0; s < 2; s++) {
        const int k0 = s << 4;
        const uint32_t ao = s * aStB, bo = s * bStB;
        CP_ASYNC16(sA0 + ao, aSrc0 + k0);
        CP_ASYNC16(sA1 + ao, aSrc1 + k0);
        CP_ASYNC16(sB0 + bo, bSrc0 + k0);
        CP_ASYNC16(sB1 + bo, bSrc1 + k0);
        CP_ASYNC16(sB2 + bo, bSrc2 + k0);
        CP_ASYNC16(sB3 + bo, bSrc3 + k0);
        CP_COMMIT();
    }

    float acc[4][8][4];
    #pragma unroll
    for (int i = 0; i < 4; i++)
        #pragma unroll
        for (int j = 0; j < 8; j++)
            #pragma unroll
            for (int k = 0; k < 4; k++) acc[i][j][k] = 0.f;

    const int aoff = (wm * 64 + q) * 20 + r;
    const int boff = (wn * 64 + q) * 20 + r;

    int rs = 0;
    for (int kt = 0; kt < KT; kt++) {
        CP_WAIT1();
        __syncthreads();

        const int kp = kt + 2;
        if (kp < KT) {
            const int k0 = kp << 4;
            const int s  = kp % 3;
            const uint32_t ao = (uint32_t)s * aStB, bo = (uint32_t)s * bStB;
            CP_ASYNC16(sA0 + ao, aSrc0 + k0);
            CP_ASYNC16(sA1 + ao, aSrc1 + k0);
            CP_ASYNC16(sB0 + bo, bSrc0 + k0);
            CP_ASYNC16(sB1 + bo, bSrc1 + k0);
            CP_ASYNC16(sB2 + bo, bSrc2 + k0);
            CP_ASYNC16(sB3 + bo, bSrc3 + k0);
        }
        CP_COMMIT();

        const float* As_s = Asm + rs * A_STAGE_F;
        const float* Bs_s = Bsm + rs * B_STAGE_F;
        #pragma unroll
        for (int ks = 0; ks < 2; ks++) {
            uint32_t a[4][4], b[8][2];
            #pragma unroll
            for (int mt = 0; mt < 4; mt++) {
                const int base = aoff + mt * 320 + ks * 8;
                a[mt][0] = __float_as_uint(As_s[base]);
                a[mt][1] = __float_as_uint(As_s[base + 160]);
                a[mt][2] = __float_as_uint(As_s[base + 4]);
                a[mt][3] = __float_as_uint(As_s[base + 164]);
            }
            #pragma unroll
            for (int nt = 0; nt < 8; nt++) {
                const int base = boff + nt * 160 + ks * 8;
                b[nt][0] = __float_as_uint(Bs_s[base]);
                b[nt][1] = __float_as_uint(Bs_s[base + 4]);
            }
            #pragma unroll
            for (int mt = 0; mt < 4; mt++)
                #pragma unroll
                for (int nt = 0; nt < 8; nt++)
                    mma_tf32(acc[mt][nt], a[mt], b[nt]);
        }
        rs++; if (rs == 3) rs = 0;
    }

    // ---- epilogue
    #pragma unroll
    for (int mt = 0; mt < 4; mt++) {
        #pragma unroll
        for (int h2 = 0; h2 < 2; h2++) {
            const int m = m0 + wm * 64 + mt * 16 + q + h2 * 8;
            if (m >= Me) continue;
            float* crow = Ce + (size_t)m * N + n0 + wn * 64;
            float rsw = 1.f;
            if (EPI == 4) rsw = rowscale[e * NTOK + m];
            #pragma unroll
            for (int nt = 0; nt < 8; nt++) {
                const int col = nt * 8 + 2 * r;
                float v0 = acc[mt][nt][h2 * 2 + 0];
                float v1 = acc[mt][nt][h2 * 2 + 1];
                if (EPI == 1 || EPI == 2) {
                    const float2 bb = *(const float2*)(bias + n0 + wn * 64 + col);
                    v0 += bb.x; v1 += bb.y;
                }
                if (EPI == 2) {
                    const float2 rr = *(const float2*)(res + (size_t)m * N + n0 + wn * 64 + col);
                    v0 += rr.x; v1 += rr.y;
                }
                if (EPI == 3) {
                    const float2 hh = *(const float2*)(other + (size_t)e * strideCe
                                                       + (size_t)m * N + n0 + wn * 64 + col);
                    v0 = (hh.x / (1.f + __expf(-hh.x))) * v0;
                    v1 = (hh.y / (1.f + __expf(-hh.y))) * v1;
                }
                if (EPI == 4) { v0 *= rsw; v1 *= rsw; }
                *(float2*)(crow + col) = make_float2(v0, v1);
            }
        }
    }
}

// ---------------- Flash attention (fp32x2 packed FFMA2, online softmax) -------
// grid: (S/128, B*H), 128 threads; each thread owns one query row.
#define FA_SMEM ((64*64 + 64*64 + 128*65) * 4)
__global__ __launch_bounds__(128) void flash_attn_kernel(
    const float* __restrict__ qkv, float* __restrict__ out)
{
    extern __shared__ float sh[];
    float* Ks = sh;
    float* Vs = sh + 64*64;
    float* Ss = sh + 2*64*64;

    const int tid = threadIdx.x;
    const int b   = blockIdx.y & 1;
    const int h   = blockIdx.y >> 1;
    const int s_q = blockIdx.x * 128 + tid;

    const size_t qbase = ((size_t)(s_q * BATCH + b)) * (3*DMODEL) + h * DHEAD;
    ull_t q2[32];
    #pragma unroll
    for (int d = 0; d < 64; d += 4) {
        float4 v = *(const float4*)(qkv + qbase + d);
        q2[d/2]     = pk2(v.x * 0.125f, v.y * 0.125f);
        q2[d/2 + 1] = pk2(v.z * 0.125f, v.w * 0.125f);
    }
    ull_t o2[32];
    #pragma unroll
    for (int d = 0; d < 32; d++) o2[d] = 0ull;
    float mrow = -1e30f, lrow = 0.f;

    for (int kt = 0; kt < S_LEN; kt += 64) {
        __syncthreads();
        for (int idx = tid; idx < 64*16; idx += 128) {
            const int rr = idx >> 4, c = (idx & 15) * 4;
            const size_t base = ((size_t)((kt + rr) * BATCH + b)) * (3*DMODEL) + h * DHEAD + c;
            *(float4*)(Ks + rr*64 + c) = *(const float4*)(qkv + DMODEL   + base);
            *(float4*)(Vs + rr*64 + c) = *(const float4*)(qkv + 2*DMODEL + base);
        }
        __syncthreads();

        // pass 1: scores s_j = q . k_j  (packed f32x2, 4 rotating accumulators)
        float mt = -1e30f;
        for (int j = 0; j < 64; j++) {
            const ulonglong2* kr = (const ulonglong2*)(Ks + j*64);
            ull_t a0 = 0ull, a1 = 0ull, a2 = 0ull, a3 = 0ull;
            #pragma unroll
            for (int i = 0; i < 8; i++) {
                ulonglong2 k0 = kr[2*i], k1 = kr[2*i + 1];
                FMA2(a0, q2[4*i    ], k0.x);
                FMA2(a1, q2[4*i + 1], k0.y);
                FMA2(a2, q2[4*i + 2], k1.x);
                FMA2(a3, q2[4*i + 3], k1.y);
            }
            ADD2(a0, a0, a1); ADD2(a2, a2, a3); ADD2(a0, a0, a2);
            float lo, hi; upk2(lo, hi, a0);
            const float s = lo + hi;
            Ss[tid*65 + j] = s;
            mt = fmaxf(mt, s);
        }

        const float mnew = fmaxf(mrow, mt);
        const float corr = __expf(mrow - mnew);
        lrow *= corr;
        {
            const ull_t pc = pk2(corr, corr);
            #pragma unroll
            for (int d = 0; d < 32; d++) { ull_t t = o2[d]; MUL2(o2[d], t, pc); }
        }

        // pass 2: o += p_j * v_j  (packed, 32 independent accumulators)
        for (int j = 0; j < 64; j++) {
            const float p = __expf(Ss[tid*65 + j] - mnew);
            lrow += p;
            const ull_t pp = pk2(p, p);
            const ulonglong2* vr = (const ulonglong2*)(Vs + j*64);
            #pragma unroll
            for (int i = 0; i < 16; i++) {
                ulonglong2 vv = vr[i];
                FMA2(o2[2*i    ], pp, vv.x);
                FMA2(o2[2*i + 1], pp, vv.y);
            }
        }
        mrow = mnew;
    }
    const float inv = 1.f / lrow;
    const size_t obase = ((size_t)(s_q * BATCH + b)) * DMODEL + h * DHEAD;
    #pragma unroll
    for (int d = 0; d < 64; d += 4) {
        float x0, x1, x2, x3;
        upk2(x0, x1, o2[d/2]);
        upk2(x2, x3, o2[d/2 + 1]);
        *(float4*)(out + obase + d) = make_float4(x0*inv, x1*inv, x2*inv, x3*inv);
    }
}

// ---------------- Router -------------------------------------------------------
__global__ void zero_cnt_kernel(int* cnt) { if (threadIdx.x < NEXP) cnt[threadIdx.x] = 0; }

__global__ __launch_bounds__(256) void router_kernel(
    const float* __restrict__ h, const float* __restrict__ gw,
    float* __restrict__ logits_out,
    int* __restrict__ rows, float* __restrict__ rwgt,
    int* __restrict__ trow, int* __restrict__ cnt)
{
    const int warp = threadIdx.x >> 5, lane = threadIdx.x & 31;
    const int t = blockIdx.x * 8 + warp;
    const float* hr = h + (size_t)t * DMODEL;
    float lg[NEXP];
    #pragma unroll
    for (int e = 0; e < NEXP; e++) {
        const float* gr = gw + e * DMODEL;
        float p = 0.f;
        for (int i = lane; i < DMODEL; i += 32) p += hr[i] * gr[i];
        #pragma unroll
        for (int off = 16; off; off >>= 1) p += __shfl_xor_sync(0xffffffffu, p, off);
        lg[e] = p;
    }
    if (lane == 0) {
        if (logits_out) {
            #pragma unroll
            for (int e = 0; e < NEXP; e++) logits_out[(size_t)t * NEXP + e] = lg[e];
        }
        float mx = lg[0];
        #pragma unroll
        for (int e = 1; e < NEXP; e++) mx = fmaxf(mx, lg[e]);
        float pr[NEXP];
        #pragma unroll
        for (int e = 0; e < NEXP; e++) pr[e] = __expf(lg[e] - mx);
        int i0 = 0;
        #pragma unroll
        for (int e = 1; e < NEXP; e++) if (pr[e] > pr[i0]) i0 = e;
        int i1 = (i0 == 0) ? 1 : 0;
        #pragma unroll
        for (int e = 0; e < NEXP; e++) if (e != i0 && pr[e] > pr[i1]) i1 = e;
        const float ws = pr[i0] + pr[i1];
        const float w0 = pr[i0] / ws, w1 = pr[i1] / ws;
        int p0 = atomicAdd(&cnt[i0], 1);
        rows[i0*NTOK + p0] = t; rwgt[i0*NTOK + p0] = w0; trow[2*t + 0] = i0*NTOK + p0;
        int p1 = atomicAdd(&cnt[i1], 1);
        rows[i1*NTOK + p1] = t; rwgt[i1*NTOK + p1] = w1; trow[2*t + 1] = i1*NTOK + p1;
    }
}

// ---------------- Final combine ------------------------------------------------
__global__ __launch_bounds__(256) void combine_kernel(
    const float* __restrict__ x2, const float* __restrict__ y,
    const int* __restrict__ trow, float* __restrict__ out)
{
    const int t = blockIdx.x;
    const int r0 = trow[2*t], r1 = trow[2*t + 1];
    const int i = threadIdx.x * 4;
    float4 a  = *(const float4*)(x2 + (size_t)t  * DMODEL + i);
    float4 y0 = *(const float4*)(y  + (size_t)r0 * DMODEL + i);
    float4 y1 = *(const float4*)(y  + (size_t)r1 * DMODEL + i);
    float4 o = make_float4(a.x + y0.x + y1.x, a.y + y0.y + y1.y,
                           a.z + y0.z + y1.z, a.w + y0.w + y1.w);
    *(float4*)(out + (size_t)t * DMODEL + i) = o;
}

// ---------------- host orchestration ------------------------------------------
extern "C" void kernel_launch(void* const* d_in, const int* in_sizes, int n_in,
                              void* d_out, int out_size)
{
    const float* x        = (const float*)d_in[0];
    const float* inproj_w = (const float*)d_in[1];
    const float* inproj_b = (const float*)d_in[2];
    const float* outproj_w= (const float*)d_in[3];
    const float* outproj_b= (const float*)d_in[4];
    const float* ln1_g    = (const float*)d_in[5];
    const float* ln1_b    = (const float*)d_in[6];
    const float* ln2_g    = (const float*)d_in[7];
    const float* ln2_b    = (const float*)d_in[8];
    const float* gate_w   = (const float*)d_in[9];
    const float* w1       = (const float*)d_in[10];
    const float* w2       = (const float*)d_in[11];
    const float* w3       = (const float*)d_in[12];

    float* out = (float*)d_out;
    float* logits_out = (out_size > NTOK * DMODEL) ? out + (size_t)NTOK * DMODEL : nullptr;

    float *p_ln1, *p_qkv, *p_attn, *p_x2, *p_ln2, *p_h1, *p_y, *p_rwgt;
    int *p_rows, *p_trow, *p_cnt;
    cudaGetSymbolAddress((void**)&p_ln1,  g_ln1);
    cudaGetSymbolAddress((void**)&p_qkv,  g_qkv);
    cudaGetSymbolAddress((void**)&p_attn, g_attn);
    cudaGetSymbolAddress((void**)&p_x2,   g_x2);
    cudaGetSymbolAddress((void**)&p_ln2,  g_ln2);
    cudaGetSymbolAddress((void**)&p_h1,   g_h1);
    cudaGetSymbolAddress((void**)&p_y,    g_y);
    cudaGetSymbolAddress((void**)&p_rwgt, g_rwgt);
    cudaGetSymbolAddress((void**)&p_rows, g_rows);
    cudaGetSymbolAddress((void**)&p_trow, g_trow);
    cudaGetSymbolAddress((void**)&p_cnt,  g_cnt);

    cudaFuncSetAttribute(gemm_tf32<1,false,false>, cudaFuncAttributeMaxDynamicSharedMemorySize, GEMM_SMEM);
    cudaFuncSetAttribute(gemm_tf32<2,false,false>, cudaFuncAttributeMaxDynamicSharedMemorySize, GEMM_SMEM);
    cudaFuncSetAttribute(gemm_tf32<0,true, true >, cudaFuncAttributeMaxDynamicSharedMemorySize, GEMM_SMEM);
    cudaFuncSetAttribute(gemm_tf32<3,true, true >, cudaFuncAttributeMaxDynamicSharedMemorySize, GEMM_SMEM);
    cudaFuncSetAttribute(gemm_tf32<4,false,true >, cudaFuncAttributeMaxDynamicSharedMemorySize, GEMM_SMEM);
    cudaFuncSetAttribute(flash_attn_kernel,        cudaFuncAttributeMaxDynamicSharedMemorySize, FA_SMEM);

    // 1. LN1
    ln_kernel<<<NTOK, 256>>>(x, ln1_g, ln1_b, p_ln1);

    // 2. QKV = ln1 @ W_in^T + b   [4096, 3072]
    gemm_tf32<1,false,false><<<dim3(3*DMODEL/256, NTOK/128), 256, GEMM_SMEM>>>(
        p_ln1, inproj_w, p_qkv, inproj_b, nullptr, nullptr, nullptr, nullptr, nullptr,
        NTOK, 3*DMODEL, DMODEL, 0, 0, 0);

    // 3. Flash attention
    flash_attn_kernel<<<dim3(S_LEN/128, BATCH*NHEAD), 128, FA_SMEM>>>(p_qkv, p_attn);

    // 4. x2 = x + attn @ W_out^T + b
    gemm_tf32<2,false,false><<<dim3(DMODEL/256, NTOK/128), 256, GEMM_SMEM>>>(
        p_attn, outproj_w, p_x2, outproj_b, x, nullptr, nullptr, nullptr, nullptr,
        NTOK, DMODEL, DMODEL, 0, 0, 0);

    // 5. LN2
    ln_kernel<<<NTOK, 256>>>(p_x2, ln2_g, ln2_b, p_ln2);

    // 6. Router
    zero_cnt_kernel<<<1, 32>>>(p_cnt);
    router_kernel<<<NTOK/8, 256>>>(p_ln2, gate_w, logits_out,
                                   p_rows, p_rwgt, p_trow, p_cnt);

    // 7. MoE expert GEMMs (grouped, gathered)
    gemm_tf32<0,true,true><<<dim3(FFN_DIM/256, NTOK/128, NEXP), 256, GEMM_SMEM>>>(
        p_ln2, w1, p_h1, nullptr, nullptr, nullptr, nullptr, p_rows, p_cnt,
        NTOK, FFN_DIM, DMODEL,
        0, (size_t)FFN_DIM*DMODEL, (size_t)NTOK*FFN_DIM);
    gemm_tf32<3,true,true><<<dim3(FFN_DIM/256, NTOK/128, NEXP), 256, GEMM_SMEM>>>(
        p_ln2, w3, p_h1, nullptr, nullptr, p_h1, nullptr, p_rows, p_cnt,
        NTOK, FFN_DIM, DMODEL,
        0, (size_t)FFN_DIM*DMODEL, (size_t)NTOK*FFN_DIM);
    gemm_tf32<4,false,true><<<dim3(DMODEL/256, NTOK/128, NEXP), 256, GEMM_SMEM>>>(
        p_h1, w2, p_y, nullptr, nullptr, nullptr, p_rwgt, nullptr, p_cnt,
        NTOK, DMODEL, FFN_DIM,
        (size_t)NTOK*FFN_DIM, (size_t)DMODEL*FFN_DIM, (size_t)NTOK*DMODEL);

    // 8. out = x2 + Y[slot0] + Y[slot1]
    combine_kernel<<<NTOK, 256>>>(p_x2, p_y, p_trow, out);
}

// round 11
// speedup vs baseline: 1.2192x; 1.2192x over previous
#include <cuda_runtime.h>
#include <cstddef>
#include <cstdint>

// Problem constants
#define S_LEN   2048
#define BATCH   2
#define DMODEL  1024
#define NHEAD   16
#define DHEAD   64
#define FFN_DIM 4096
#define NEXP    8
#define NTOK    (S_LEN*BATCH)          // 4096 tokens, t = s*BATCH + b

// ---------------- scratch (static device globals; no runtime allocation) ----
__device__ float g_ln1 [(size_t)NTOK*DMODEL];
__device__ float g_qkv [(size_t)NTOK*3*DMODEL];
__device__ float g_attn[(size_t)NTOK*DMODEL];
__device__ float g_x2  [(size_t)NTOK*DMODEL];
__device__ float g_ln2 [(size_t)NTOK*DMODEL];
__device__ float g_h1  [(size_t)NEXP*NTOK*FFN_DIM];   // expert hidden
__device__ float g_y   [(size_t)NEXP*NTOK*DMODEL];    // expert outputs
__device__ int   g_rows[NEXP*NTOK];
__device__ float g_rwgt[NEXP*NTOK];
__device__ int   g_trow[2*NTOK];
__device__ int   g_cnt [NEXP];

// ---------------- helpers ----------------------------------------------------
__device__ __forceinline__ uint32_t smem_u32(const void* p) {
    return (uint32_t)__cvta_generic_to_shared(p);
}
#define CP_ASYNC16(dst, src) \
    asm volatile("cp.async.cg.shared.global [%0], [%1], 16;\n" :: "r"(dst), "l"(src))
#define CP_COMMIT()  asm volatile("cp.async.commit_group;\n")
#define CP_WAIT1()   asm volatile("cp.async.wait_group 1;\n")

__device__ __forceinline__ void mma_tf32(float c[4], const uint32_t a[4], const uint32_t b[2]) {
    asm volatile(
        "mma.sync.aligned.m16n8k8.row.col.f32.tf32.tf32.f32 "
        "{%0,%1,%2,%3}, {%4,%5,%6,%7}, {%8,%9}, {%0,%1,%2,%3};"
        : "+f"(c[0]), "+f"(c[1]), "+f"(c[2]), "+f"(c[3])
        : "r"(a[0]), "r"(a[1]), "r"(a[2]), "r"(a[3]), "r"(b[0]), "r"(b[1]));
}

// packed fp32x2 (Blackwell FFMA2 — baseline sm_100-family PTX, no 'a' needed)
typedef unsigned long long ull_t;
#define FMA2(d, a, b) \
    asm("fma.rn.f32x2 %0, %1, %2, %0;" : "+l"(d) : "l"(a), "l"(b))
#define ADD2(d, a, b) \
    asm("add.rn.f32x2 %0, %1, %2;" : "=l"(d) : "l"(a), "l"(b))
#define MUL2(d, a, b) \
    asm("mul.rn.f32x2 %0, %1, %2;" : "=l"(d) : "l"(a), "l"(b))
__device__ __forceinline__ ull_t pk2(float lo, float hi) {
    ull_t r; asm("mov.b64 %0, {%1, %2};" : "=l"(r) : "f"(lo), "f"(hi)); return r;
}
__device__ __forceinline__ void upk2(float& lo, float& hi, ull_t v) {
    asm("mov.b64 {%0, %1}, %2;" : "=f"(lo), "=f"(hi) : "l"(v));
}

// ---------------- LayerNorm: one block per token row --------------------------
__global__ __launch_bounds__(256) void ln_kernel(
    const float* __restrict__ x, const float* __restrict__ g,
    const float* __restrict__ b, float* __restrict__ y)
{
    const int t   = blockIdx.x;
    const int tid = threadIdx.x;
    const float* xr = x + (size_t)t * DMODEL;
    float4 v = *(const float4*)(xr + tid * 4);
    float s  = v.x + v.y + v.z + v.w;
    float s2 = v.x*v.x + v.y*v.y + v.z*v.z + v.w*v.w;
    __shared__ float red[64];
    const int lane = tid & 31, wid = tid >> 5;
    #pragma unroll
    for (int off = 16; off; off >>= 1) {
        s  += __shfl_down_sync(0xffffffffu, s,  off);
        s2 += __shfl_down_sync(0xffffffffu, s2, off);
    }
    if (lane == 0) { red[wid] = s; red[32 + wid] = s2; }
    __syncthreads();
    if (tid == 0) {
        float ts = 0.f, ts2 = 0.f;
        #pragma unroll
        for (int i = 0; i < 8; i++) { ts += red[i]; ts2 += red[32 + i]; }
        float mean = ts * (1.f / DMODEL);
        float var  = ts2 * (1.f / DMODEL) - mean * mean;
        red[16] = mean;
        red[17] = rsqrtf(var + 1e-5f);
    }
    __syncthreads();
    const float mean = red[16], rstd = red[17];
    float4 gg = *(const float4*)(g + tid * 4);
    float4 bb = *(const float4*)(b + tid * 4);
    float4 o;
    o.x = (v.x - mean) * rstd * gg.x + bb.x;
    o.y = (v.y - mean) * rstd * gg.y + bb.y;
    o.z = (v.z - mean) * rstd * gg.z + bb.z;
    o.w = (v.w - mean) * rstd * gg.w + bb.w;
    *(float4*)(y + (size_t)t * DMODEL + tid * 4) = o;
}

// ---------------- TF32 tensor-core GEMM (128x128 tile, BK=32) -----------------
// C[m,n] = sum_k A[m,k] * B[n,k]  (row-major A, row-major B as [N][K])
// BK=32, 3-stage cp.async pipeline, 256 threads = 8 warps (2m x 4n),
// each warp 64x32 via m16n8k8 tf32 (4 m-frags x 4 n-frags x 4 k-steps/iter).
// smem: [row][36] layout (144B row stride, 16B-aligned, conflict-free frags).
// __launch_bounds__(256,2) -> <=128 regs -> 2 CTAs/SM (216KB smem of 228KB).
// EPI: 0 plain, 1 +bias, 2 +bias+res, 3 silu(other)*acc, 4 rowscale*acc
#define TILE_ROW_F 36
#define A_STAGE_F  (128 * TILE_ROW_F)            // 4608 floats
#define B_STAGE_F  (128 * TILE_ROW_F)            // 4608 floats
#define GEMM_SMEM  (3 * (A_STAGE_F + B_STAGE_F) * 4)   // 110592 B

template<int EPI, bool GATHER, bool GROUPED>
__global__ __launch_bounds__(256, 2) void gemm_tf32(
    const float* __restrict__ A, const float* __restrict__ Bw, float* __restrict__ C,
    const float* __restrict__ bias, const float* __restrict__ res,
    const float* __restrict__ other, const float* __restrict__ rowscale,
    const int* __restrict__ rowsIdx, const int* __restrict__ cnt,
    int M, int N, int K,
    size_t strideAe, size_t strideBe, size_t strideCe)
{
    const int e  = GROUPED ? blockIdx.z : 0;
    int Me = M;
    if (GROUPED && cnt) Me = cnt[e];
    const int m0 = blockIdx.y * 128;
    if (m0 >= Me) return;
    const int n0 = blockIdx.x * 128;

    const float* Ae = A  + (size_t)e * strideAe;
    const float* Be = Bw + (size_t)e * strideBe;
    float*       Ce = C  + (size_t)e * strideCe;

    extern __shared__ float sh[];
    float* Asm = sh;                             // [3][128][36]
    float* Bsm = sh + 3 * A_STAGE_F;             // [3][128][36]

    const int tid  = threadIdx.x;
    const int lane = tid & 31, wid = tid >> 5;
    const int wm = wid >> 2, wn = wid & 3;       // warp grid 2 x 4
    const int q  = lane >> 2, r = lane & 3;

    // ---- staging: BK=32 -> 8 chunks of 16B per row; thread owns 4 A + 4 B chunks
    const int ldRow0 = tid >> 3;                 // 0..31
    const int seg    = tid & 7;                  // chunk 0..7 -> float offset seg*4
    const float* aSrc[4];
    const float* bSrc[4];
    #pragma unroll
    for (int it = 0; it < 4; it++) {
        int am = m0 + ldRow0 + it * 32;
        if (am >= Me) am = Me - 1;
        const size_t ar = GATHER ? (size_t)rowsIdx[e * NTOK + am] : (size_t)am;
        aSrc[it] = Ae + ar * K + seg * 4;
        bSrc[it] = Be + (size_t)(n0 + ldRow0 + it * 32) * K + seg * 4;
    }
    const uint32_t stB = (A_STAGE_F + B_STAGE_F) * 4;   // bytes per stage pair
    const uint32_t sAb = smem_u32(Asm) + (uint32_t)(ldRow0 * TILE_ROW_F + seg * 4) * 4;
    const uint32_t sBb = smem_u32(Bsm) + (uint32_t)(ldRow0 * TILE_ROW_F + seg * 4) * 4;
    const uint32_t rowStep = 32 * TILE_ROW_F * 4;       // 32 rows in bytes

    const int KT = K >> 5;                       // #BK=32 iterations

    // prefetch stages 0,1
    #pragma unroll
    for (int s = 0; s < 2; s++) {
        const int k0 = s << 5;
        const uint32_t ao = s * (A_STAGE_F * 4);
        const uint32_t bo = s * (B_STAGE_F * 4);
        #pragma unroll
        for (int it = 0; it < 4; it++) {
            CP_ASYNC16(sAb + ao + it * rowStep, aSrc[it] + k0);
            CP_ASYNC16(sBb + bo + it * rowStep, bSrc[it] + k0);
        }
        CP_COMMIT();
    }

    float acc[4][4][4];
    #pragma unroll
    for (int i = 0; i < 4; i++)
        #pragma unroll
        for (int j = 0; j < 4; j++)
            #pragma unroll
            for (int k = 0; k < 4; k++) acc[i][j][k] = 0.f;

    const int aoff = (wm * 64 + q) * TILE_ROW_F + r;
    const int boff = (wn * 32 + q) * TILE_ROW_F + r;

    int rs = 0;
    for (int kt = 0; kt < KT; kt++) {
        CP_WAIT1();
        __syncthreads();

        const int kp = kt + 2;
        if (kp < KT) {
            const int k0 = kp << 5;
            const int s  = kp % 3;
            const uint32_t ao = (uint32_t)s * (A_STAGE_F * 4);
            const uint32_t bo = (uint32_t)s * (B_STAGE_F * 4);
            #pragma unroll
            for (int it = 0; it < 4; it++) {
                CP_ASYNC16(sAb + ao + it * rowStep, aSrc[it] + k0);
                CP_ASYNC16(sBb + bo + it * rowStep, bSrc[it] + k0);
            }
        }
        CP_COMMIT();

        const float* As_s = Asm + rs * A_STAGE_F;
        const float* Bs_s = Bsm + rs * B_STAGE_F;
        #pragma unroll
        for (int ks = 0; ks < 4; ks++) {
            uint32_t a[4][4], b[4][2];
            #pragma unroll
            for (int mt = 0; mt < 4; mt++) {
                const int base = aoff + mt * 16 * TILE_ROW_F + ks * 8;
                a[mt][0] = __float_as_uint(As_s[base]);
                a[mt][1] = __float_as_uint(As_s[base + 8 * TILE_ROW_F]);
                a[mt][2] = __float_as_uint(As_s[base + 4]);
                a[mt][3] = __float_as_uint(As_s[base + 8 * TILE_ROW_F + 4]);
            }
            #pragma unroll
            for (int nt = 0; nt < 4; nt++) {
                const int base = boff + nt * 8 * TILE_ROW_F + ks * 8;
                b[nt][0] = __float_as_uint(Bs_s[base]);
                b[nt][1] = __float_as_uint(Bs_s[base + 4]);
            }
            #pragma unroll
            for (int mt = 0; mt < 4; mt++)
                #pragma unroll
                for (int nt = 0; nt < 4; nt++)
                    mma_tf32(acc[mt][nt], a[mt], b[nt]);
        }
        rs++; if (rs == 3) rs = 0;
    }

    // ---- epilogue
    #pragma unroll
    for (int mt = 0; mt < 4; mt++) {
        #pragma unroll
        for (int h2 = 0; h2 < 2; h2++) {
            const int m = m0 + wm * 64 + mt * 16 + q + h2 * 8;
            if (m >= Me) continue;
            float* crow = Ce + (size_t)m * N + n0 + wn * 32;
            float rsw = 1.f;
            if (EPI == 4) rsw = rowscale[e * NTOK + m];
            #pragma unroll
            for (int nt = 0; nt < 4; nt++) {
                const int col = nt * 8 + 2 * r;
                float v0 = acc[mt][nt][h2 * 2 + 0];
                float v1 = acc[mt][nt][h2 * 2 + 1];
                if (EPI == 1 || EPI == 2) {
                    const float2 bb = *(const float2*)(bias + n0 + wn * 32 + col);
                    v0 += bb.x; v1 += bb.y;
                }
                if (EPI == 2) {
                    const float2 rr = *(const float2*)(res + (size_t)m * N + n0 + wn * 32 + col);
                    v0 += rr.x; v1 += rr.y;
                }
                if (EPI == 3) {
                    const float2 hh = *(const float2*)(other + (size_t)e * strideCe
                                                       + (size_t)m * N + n0 + wn * 32 + col);
                    v0 = (hh.x / (1.f + __expf(-hh.x))) * v0;
                    v1 = (hh.y / (1.f + __expf(-hh.y))) * v1;
                }
                if (EPI == 4) { v0 *= rsw; v1 *= rsw; }
                *(float2*)(crow + col) = make_float2(v0, v1);
            }
        }
    }
}

// ---------------- Flash attention (fp32x2 packed FFMA2, online softmax) -------
// grid: (S/128, B*H), 128 threads; each thread owns one query row.
#define FA_SMEM ((64*64 + 64*64 + 128*65) * 4)
__global__ __launch_bounds__(128) void flash_attn_kernel(
    const float* __restrict__ qkv, float* __restrict__ out)
{
    extern __shared__ float sh[];
    float* Ks = sh;
    float* Vs = sh + 64*64;
    float* Ss = sh + 2*64*64;

    const int tid = threadIdx.x;
    const int b   = blockIdx.y & 1;
    const int h   = blockIdx.y >> 1;
    const int s_q = blockIdx.x * 128 + tid;

    const size_t qbase = ((size_t)(s_q * BATCH + b)) * (3*DMODEL) + h * DHEAD;
    ull_t q2[32];
    #pragma unroll
    for (int d = 0; d < 64; d += 4) {
        float4 v = *(const float4*)(qkv + qbase + d);
        q2[d/2]     = pk2(v.x * 0.125f, v.y * 0.125f);
        q2[d/2 + 1] = pk2(v.z * 0.125f, v.w * 0.125f);
    }
    ull_t o2[32];
    #pragma unroll
    for (int d = 0; d < 32; d++) o2[d] = 0ull;
    float mrow = -1e30f, lrow = 0.f;

    for (int kt = 0; kt < S_LEN; kt += 64) {
        __syncthreads();
        for (int idx = tid; idx < 64*16; idx += 128) {
            const int rr = idx >> 4, c = (idx & 15) * 4;
            const size_t base = ((size_t)((kt + rr) * BATCH + b)) * (3*DMODEL) + h * DHEAD + c;
            *(float4*)(Ks + rr*64 + c) = *(const float4*)(qkv + DMODEL   + base);
            *(float4*)(Vs + rr*64 + c) = *(const float4*)(qkv + 2*DMODEL + base);
        }
        __syncthreads();

        // pass 1: scores s_j = q . k_j  (packed f32x2, 4 rotating accumulators)
        float mt = -1e30f;
        for (int j = 0; j < 64; j++) {
            const ulonglong2* kr = (const ulonglong2*)(Ks + j*64);
            ull_t a0 = 0ull, a1 = 0ull, a2 = 0ull, a3 = 0ull;
            #pragma unroll
            for (int i = 0; i < 8; i++) {
                ulonglong2 k0 = kr[2*i], k1 = kr[2*i + 1];
                FMA2(a0, q2[4*i    ], k0.x);
                FMA2(a1, q2[4*i + 1], k0.y);
                FMA2(a2, q2[4*i + 2], k1.x);
                FMA2(a3, q2[4*i + 3], k1.y);
            }
            ADD2(a0, a0, a1); ADD2(a2, a2, a3); ADD2(a0, a0, a2);
            float lo, hi; upk2(lo, hi, a0);
            const float s = lo + hi;
            Ss[tid*65 + j] = s;
            mt = fmaxf(mt, s);
        }

        const float mnew = fmaxf(mrow, mt);
        const float corr = __expf(mrow - mnew);
        lrow *= corr;
        {
            const ull_t pc = pk2(corr, corr);
            #pragma unroll
            for (int d = 0; d < 32; d++) { ull_t t = o2[d]; MUL2(o2[d], t, pc); }
        }

        // pass 2: o += p_j * v_j  (packed, 32 independent accumulators)
        for (int j = 0; j < 64; j++) {
            const float p = __expf(Ss[tid*65 + j] - mnew);
            lrow += p;
            const ull_t pp = pk2(p, p);
            const ulonglong2* vr = (const ulonglong2*)(Vs + j*64);
            #pragma unroll
            for (int i = 0; i < 16; i++) {
                ulonglong2 vv = vr[i];
                FMA2(o2[2*i    ], pp, vv.x);
                FMA2(o2[2*i + 1], pp, vv.y);
            }
        }
        mrow = mnew;
    }
    const float inv = 1.f / lrow;
    const size_t obase = ((size_t)(s_q * BATCH + b)) * DMODEL + h * DHEAD;
    #pragma unroll
    for (int d = 0; d < 64; d += 4) {
        float x0, x1, x2, x3;
        upk2(x0, x1, o2[d/2]);
        upk2(x2, x3, o2[d/2 + 1]);
        *(float4*)(out + obase + d) = make_float4(x0*inv, x1*inv, x2*inv, x3*inv);
    }
}

// ---------------- Router -------------------------------------------------------
__global__ void zero_cnt_kernel(int* cnt) { if (threadIdx.x < NEXP) cnt[threadIdx.x] = 0; }

__global__ __launch_bounds__(256) void router_kernel(
    const float* __restrict__ h, const float* __restrict__ gw,
    float* __restrict__ logits_out,
    int* __restrict__ rows, float* __restrict__ rwgt,
    int* __restrict__ trow, int* __restrict__ cnt)
{
    const int warp = threadIdx.x >> 5, lane = threadIdx.x & 31;
    const int t = blockIdx.x * 8 + warp;
    const float* hr = h + (size_t)t * DMODEL;
    float lg[NEXP];
    #pragma unroll
    for (int e = 0; e < NEXP; e++) {
        const float* gr = gw + e * DMODEL;
        float p = 0.f;
        for (int i = lane; i < DMODEL; i += 32) p += hr[i] * gr[i];
        #pragma unroll
        for (int off = 16; off; off >>= 1) p += __shfl_xor_sync(0xffffffffu, p, off);
        lg[e] = p;
    }
    if (lane == 0) {
        if (logits_out) {
            #pragma unroll
            for (int e = 0; e < NEXP; e++) logits_out[(size_t)t * NEXP + e] = lg[e];
        }
        float mx = lg[0];
        #pragma unroll
        for (int e = 1; e < NEXP; e++) mx = fmaxf(mx, lg[e]);
        float pr[NEXP];
        #pragma unroll
        for (int e = 0; e < NEXP; e++) pr[e] = __expf(lg[e] - mx);
        int i0 = 0;
        #pragma unroll
        for (int e = 1; e < NEXP; e++) if (pr[e] > pr[i0]) i0 = e;
        int i1 = (i0 == 0) ? 1 : 0;
        #pragma unroll
        for (int e = 0; e < NEXP; e++) if (e != i0 && pr[e] > pr[i1]) i1 = e;
        const float ws = pr[i0] + pr[i1];
        const float w0 = pr[i0] / ws, w1 = pr[i1] / ws;
        int p0 = atomicAdd(&cnt[i0], 1);
        rows[i0*NTOK + p0] = t; rwgt[i0*NTOK + p0] = w0; trow[2*t + 0] = i0*NTOK + p0;
        int p1 = atomicAdd(&cnt[i1], 1);
        rows[i1*NTOK + p1] = t; rwgt[i1*NTOK + p1] = w1; trow[2*t + 1] = i1*NTOK + p1;
    }
}

// ---------------- Final combine ------------------------------------------------
__global__ __launch_bounds__(256) void combine_kernel(
    const float* __restrict__ x2, const float* __restrict__ y,
    const int* __restrict__ trow, float* __restrict__ out)
{
    const int t = blockIdx.x;
    const int r0 = trow[2*t], r1 = trow[2*t + 1];
    const int i = threadIdx.x * 4;
    float4 a  = *(const float4*)(x2 + (size_t)t  * DMODEL + i);
    float4 y0 = *(const float4*)(y  + (size_t)r0 * DMODEL + i);
    float4 y1 = *(const float4*)(y  + (size_t)r1 * DMODEL + i);
    float4 o = make_float4(a.x + y0.x + y1.x, a.y + y0.y + y1.y,
                           a.z + y0.z + y1.z, a.w + y0.w + y1.w);
    *(float4*)(out + (size_t)t * DMODEL + i) = o;
}

// ---------------- host orchestration ------------------------------------------
extern "C" void kernel_launch(void* const* d_in, const int* in_sizes, int n_in,
                              void* d_out, int out_size)
{
    const float* x        = (const float*)d_in[0];
    const float* inproj_w = (const float*)d_in[1];
    const float* inproj_b = (const float*)d_in[2];
    const float* outproj_w= (const float*)d_in[3];
    const float* outproj_b= (const float*)d_in[4];
    const float* ln1_g    = (const float*)d_in[5];
    const float* ln1_b    = (const float*)d_in[6];
    const float* ln2_g    = (const float*)d_in[7];
    const float* ln2_b    = (const float*)d_in[8];
    const float* gate_w   = (const float*)d_in[9];
    const float* w1       = (const float*)d_in[10];
    const float* w2       = (const float*)d_in[11];
    const float* w3       = (const float*)d_in[12];

    float* out = (float*)d_out;
    float* logits_out = (out_size > NTOK * DMODEL) ? out + (size_t)NTOK * DMODEL : nullptr;

    float *p_ln1, *p_qkv, *p_attn, *p_x2, *p_ln2, *p_h1, *p_y, *p_rwgt;
    int *p_rows, *p_trow, *p_cnt;
    cudaGetSymbolAddress((void**)&p_ln1,  g_ln1);
    cudaGetSymbolAddress((void**)&p_qkv,  g_qkv);
    cudaGetSymbolAddress((void**)&p_attn, g_attn);
    cudaGetSymbolAddress((void**)&p_x2,   g_x2);
    cudaGetSymbolAddress((void**)&p_ln2,  g_ln2);
    cudaGetSymbolAddress((void**)&p_h1,   g_h1);
    cudaGetSymbolAddress((void**)&p_y,    g_y);
    cudaGetSymbolAddress((void**)&p_rwgt, g_rwgt);
    cudaGetSymbolAddress((void**)&p_rows, g_rows);
    cudaGetSymbolAddress((void**)&p_trow, g_trow);
    cudaGetSymbolAddress((void**)&p_cnt,  g_cnt);

    cudaFuncSetAttribute(gemm_tf32<1,false,false>, cudaFuncAttributeMaxDynamicSharedMemorySize, GEMM_SMEM);
    cudaFuncSetAttribute(gemm_tf32<2,false,false>, cudaFuncAttributeMaxDynamicSharedMemorySize, GEMM_SMEM);
    cudaFuncSetAttribute(gemm_tf32<0,true, true >, cudaFuncAttributeMaxDynamicSharedMemorySize, GEMM_SMEM);
    cudaFuncSetAttribute(gemm_tf32<3,true, true >, cudaFuncAttributeMaxDynamicSharedMemorySize, GEMM_SMEM);
    cudaFuncSetAttribute(gemm_tf32<4,false,true >, cudaFuncAttributeMaxDynamicSharedMemorySize, GEMM_SMEM);
    cudaFuncSetAttribute(flash_attn_kernel,        cudaFuncAttributeMaxDynamicSharedMemorySize, FA_SMEM);

    // 1. LN1
    ln_kernel<<<NTOK, 256>>>(x, ln1_g, ln1_b, p_ln1);

    // 2. QKV = ln1 @ W_in^T + b   [4096, 3072]
    gemm_tf32<1,false,false><<<dim3(3*DMODEL/128, NTOK/128), 256, GEMM_SMEM>>>(
        p_ln1, inproj_w, p_qkv, inproj_b, nullptr, nullptr, nullptr, nullptr, nullptr,
        NTOK, 3*DMODEL, DMODEL, 0, 0, 0);

    // 3. Flash attention
    flash_attn_kernel<<<dim3(S_LEN/128, BATCH*NHEAD), 128, FA_SMEM>>>(p_qkv, p_attn);

    // 4. x2 = x + attn @ W_out^T + b
    gemm_tf32<2,false,false><<<dim3(DMODEL/128, NTOK/128), 256, GEMM_SMEM>>>(
        p_attn, outproj_w, p_x2, outproj_b, x, nullptr, nullptr, nullptr, nullptr,
        NTOK, DMODEL, DMODEL, 0, 0, 0);

    // 5. LN2
    ln_kernel<<<NTOK, 256>>>(p_x2, ln2_g, ln2_b, p_ln2);

    // 6. Router
    zero_cnt_kernel<<<1, 32>>>(p_cnt);
    router_kernel<<<NTOK/8, 256>>>(p_ln2, gate_w, logits_out,
                                   p_rows, p_rwgt, p_trow, p_cnt);

    // 7. MoE expert GEMMs (grouped, gathered)
    gemm_tf32<0,true,true><<<dim3(FFN_DIM/128, NTOK/128, NEXP), 256, GEMM_SMEM>>>(
        p_ln2, w1, p_h1, nullptr, nullptr, nullptr, nullptr, p_rows, p_cnt,
        NTOK, FFN_DIM, DMODEL,
        0, (size_t)FFN_DIM*DMODEL, (size_t)NTOK*FFN_DIM);
    gemm_tf32<3,true,true><<<dim3(FFN_DIM/128, NTOK/128, NEXP), 256, GEMM_SMEM>>>(
        p_ln2, w3, p_h1, nullptr, nullptr, p_h1, nullptr, p_rows, p_cnt,
        NTOK, FFN_DIM, DMODEL,
        0, (size_t)FFN_DIM*DMODEL, (size_t)NTOK*FFN_DIM);
    gemm_tf32<4,false,true><<<dim3(DMODEL/128, NTOK/128, NEXP), 256, GEMM_SMEM>>>(
        p_h1, w2, p_y, nullptr, nullptr, nullptr, p_rwgt, nullptr, p_cnt,
        NTOK, DMODEL, FFN_DIM,
        (size_t)NTOK*FFN_DIM, (size_t)DMODEL*FFN_DIM, (size_t)NTOK*DMODEL);

    // 8. out = x2 + Y[slot0] + Y[slot1]
    combine_kernel<<<NTOK, 256>>>(p_x2, p_y, p_trow, out);
}

// round 12
// speedup vs baseline: 1.2305x; 1.0093x over previous
#include <cuda_runtime.h>
#include <cstddef>
#include <cstdint>

// Problem constants
#define S_LEN   2048
#define BATCH   2
#define DMODEL  1024
#define NHEAD   16
#define DHEAD   64
#define FFN_DIM 4096
#define NEXP    8
#define NTOK    (S_LEN*BATCH)          // 4096 tokens, t = s*BATCH + b

// ---------------- scratch (static device globals; no runtime allocation) ----
__device__ float g_ln1 [(size_t)NTOK*DMODEL];
__device__ float g_qkv [(size_t)NTOK*3*DMODEL];
__device__ float g_attn[(size_t)NTOK*DMODEL];
__device__ float g_x2  [(size_t)NTOK*DMODEL];
__device__ float g_ln2 [(size_t)NTOK*DMODEL];
__device__ float g_h1  [(size_t)NEXP*NTOK*FFN_DIM];   // expert hidden
__device__ float g_y   [(size_t)NEXP*NTOK*DMODEL];    // expert outputs
__device__ int   g_rows[NEXP*NTOK];
__device__ float g_rwgt[NEXP*NTOK];
__device__ int   g_trow[2*NTOK];
__device__ int   g_cnt [NEXP];

// ---------------- helpers ----------------------------------------------------
__device__ __forceinline__ uint32_t smem_u32(const void* p) {
    return (uint32_t)__cvta_generic_to_shared(p);
}
#define CP_ASYNC16(dst, src) \
    asm volatile("cp.async.cg.shared.global [%0], [%1], 16;\n" :: "r"(dst), "l"(src))
#define CP_COMMIT()  asm volatile("cp.async.commit_group;\n")
#define CP_WAIT1()   asm volatile("cp.async.wait_group 1;\n")

#define LDSM4(r0, r1, r2, r3, addr) \
    asm volatile("ldmatrix.sync.aligned.m8n8.x4.shared.b16 {%0,%1,%2,%3}, [%4];" \
        : "=r"(r0), "=r"(r1), "=r"(r2), "=r"(r3) : "r"(addr))
#define LDSM2(r0, r1, addr) \
    asm volatile("ldmatrix.sync.aligned.m8n8.x2.shared.b16 {%0,%1}, [%2];" \
        : "=r"(r0), "=r"(r1) : "r"(addr))

__device__ __forceinline__ void mma_tf32(float c[4], const uint32_t a[4], const uint32_t b[2]) {
    asm volatile(
        "mma.sync.aligned.m16n8k8.row.col.f32.tf32.tf32.f32 "
        "{%0,%1,%2,%3}, {%4,%5,%6,%7}, {%8,%9}, {%0,%1,%2,%3};"
        : "+f"(c[0]), "+f"(c[1]), "+f"(c[2]), "+f"(c[3])
        : "r"(a[0]), "r"(a[1]), "r"(a[2]), "r"(a[3]), "r"(b[0]), "r"(b[1]));
}

// packed fp32x2 (Blackwell FFMA2 — baseline sm_100-family PTX, no 'a' needed)
typedef unsigned long long ull_t;
#define FMA2(d, a, b) \
    asm("fma.rn.f32x2 %0, %1, %2, %0;" : "+l"(d) : "l"(a), "l"(b))
#define ADD2(d, a, b) \
    asm("add.rn.f32x2 %0, %1, %2;" : "=l"(d) : "l"(a), "l"(b))
#define MUL2(d, a, b) \
    asm("mul.rn.f32x2 %0, %1, %2;" : "=l"(d) : "l"(a), "l"(b))
__device__ __forceinline__ ull_t pk2(float lo, float hi) {
    ull_t r; asm("mov.b64 %0, {%1, %2};" : "=l"(r) : "f"(lo), "f"(hi)); return r;
}
__device__ __forceinline__ void upk2(float& lo, float& hi, ull_t v) {
    asm("mov.b64 {%0, %1}, %2;" : "=f"(lo), "=f"(hi) : "l"(v));
}

// ---------------- LayerNorm: one block per token row --------------------------
__global__ __launch_bounds__(256) void ln_kernel(
    const float* __restrict__ x, const float* __restrict__ g,
    const float* __restrict__ b, float* __restrict__ y)
{
    const int t   = blockIdx.x;
    const int tid = threadIdx.x;
    const float* xr = x + (size_t)t * DMODEL;
    float4 v = *(const float4*)(xr + tid * 4);
    float s  = v.x + v.y + v.z + v.w;
    float s2 = v.x*v.x + v.y*v.y + v.z*v.z + v.w*v.w;
    __shared__ float red[64];
    const int lane = tid & 31, wid = tid >> 5;
    #pragma unroll
    for (int off = 16; off; off >>= 1) {
        s  += __shfl_down_sync(0xffffffffu, s,  off);
        s2 += __shfl_down_sync(0xffffffffu, s2, off);
    }
    if (lane == 0) { red[wid] = s; red[32 + wid] = s2; }
    __syncthreads();
    if (tid == 0) {
        float ts = 0.f, ts2 = 0.f;
        #pragma unroll
        for (int i = 0; i < 8; i++) { ts += red[i]; ts2 += red[32 + i]; }
        float mean = ts * (1.f / DMODEL);
        float var  = ts2 * (1.f / DMODEL) - mean * mean;
        red[16] = mean;
        red[17] = rsqrtf(var + 1e-5f);
    }
    __syncthreads();
    const float mean = red[16], rstd = red[17];
    float4 gg = *(const float4*)(g + tid * 4);
    float4 bb = *(const float4*)(b + tid * 4);
    float4 o;
    o.x = (v.x - mean) * rstd * gg.x + bb.x;
    o.y = (v.y - mean) * rstd * gg.y + bb.y;
    o.z = (v.z - mean) * rstd * gg.z + bb.z;
    o.w = (v.w - mean) * rstd * gg.w + bb.w;
    *(float4*)(y + (size_t)t * DMODEL + tid * 4) = o;
}

// ---------------- TF32 tensor-core GEMM (128x128 tile, BK=32, ldmatrix) -------
// C[m,n] = sum_k A[m,k] * B[n,k]  (row-major A, row-major B as [N][K])
// BK=32, 3-stage cp.async pipeline, 256 threads = 8 warps (2m x 4n),
// each warp 64x32 via m16n8k8 tf32 (4 m-frags x 4 n-frags x 4 k-steps/iter).
// Fragment loads via ldmatrix m8n8 (.x4 for A, .x2 for B) — 32 LDSM vs 96 LDS.
// smem: [row][36] layout (144B row stride; LDSM rows tile 128B -> conflict-free).
// __launch_bounds__(256,2) -> <=128 regs -> 2 CTAs/SM (216KB smem of 228KB).
// EPI: 0 plain, 1 +bias, 2 +bias+res, 3 silu(other)*acc, 4 rowscale*acc
#define TILE_ROW_F 36
#define A_STAGE_F  (128 * TILE_ROW_F)            // 4608 floats
#define B_STAGE_F  (128 * TILE_ROW_F)            // 4608 floats
#define GEMM_SMEM  (3 * (A_STAGE_F + B_STAGE_F) * 4)   // 110592 B

template<int EPI, bool GATHER, bool GROUPED>
__global__ __launch_bounds__(256, 2) void gemm_tf32(
    const float* __restrict__ A, const float* __restrict__ Bw, float* __restrict__ C,
    const float* __restrict__ bias, const float* __restrict__ res,
    const float* __restrict__ other, const float* __restrict__ rowscale,
    const int* __restrict__ rowsIdx, const int* __restrict__ cnt,
    int M, int N, int K,
    size_t strideAe, size_t strideBe, size_t strideCe)
{
    const int e  = GROUPED ? blockIdx.z : 0;
    int Me = M;
    if (GROUPED && cnt) Me = cnt[e];
    const int m0 = blockIdx.y * 128;
    if (m0 >= Me) return;
    const int n0 = blockIdx.x * 128;

    const float* Ae = A  + (size_t)e * strideAe;
    const float* Be = Bw + (size_t)e * strideBe;
    float*       Ce = C  + (size_t)e * strideCe;

    extern __shared__ float sh[];
    float* Asm = sh;                             // [3][128][36]
    float* Bsm = sh + 3 * A_STAGE_F;             // [3][128][36]

    const int tid  = threadIdx.x;
    const int lane = tid & 31, wid = tid >> 5;
    const int wm = wid >> 2, wn = wid & 3;       // warp grid 2 x 4
    const int q  = lane >> 2, r = lane & 3;

    // ---- staging: BK=32 -> 8 chunks of 16B per row; thread owns 4 A + 4 B chunks
    const int ldRow0 = tid >> 3;                 // 0..31
    const int seg    = tid & 7;                  // chunk 0..7 -> float offset seg*4
    const float* aSrc[4];
    const float* bSrc[4];
    #pragma unroll
    for (int it = 0; it < 4; it++) {
        int am = m0 + ldRow0 + it * 32;
        if (am >= Me) am = Me - 1;
        const size_t ar = GATHER ? (size_t)rowsIdx[e * NTOK + am] : (size_t)am;
        aSrc[it] = Ae + ar * K + seg * 4;
        bSrc[it] = Be + (size_t)(n0 + ldRow0 + it * 32) * K + seg * 4;
    }
    const uint32_t sAb = smem_u32(Asm) + (uint32_t)(ldRow0 * TILE_ROW_F + seg * 4) * 4;
    const uint32_t sBb = smem_u32(Bsm) + (uint32_t)(ldRow0 * TILE_ROW_F + seg * 4) * 4;
    const uint32_t rowStep = 32 * TILE_ROW_F * 4;       // 32 rows in bytes

    const int KT = K >> 5;                       // #BK=32 iterations

    // prefetch stages 0,1
    #pragma unroll
    for (int s = 0; s < 2; s++) {
        const int k0 = s << 5;
        const uint32_t ao = s * (A_STAGE_F * 4);
        const uint32_t bo = s * (B_STAGE_F * 4);
        #pragma unroll
        for (int it = 0; it < 4; it++) {
            CP_ASYNC16(sAb + ao + it * rowStep, aSrc[it] + k0);
            CP_ASYNC16(sBb + bo + it * rowStep, bSrc[it] + k0);
        }
        CP_COMMIT();
    }

    float acc[4][4][4];
    #pragma unroll
    for (int i = 0; i < 4; i++)
        #pragma unroll
        for (int j = 0; j < 4; j++)
            #pragma unroll
            for (int k = 0; k < 4; k++) acc[i][j][k] = 0.f;

    // ldmatrix per-thread base offsets (bytes, within a stage):
    // A .x4: lanes 0-7 rows 0-7/kgrp0, 8-15 rows 8-15/kgrp0, 16-23 rows 0-7/kgrp1, 24-31 rows 8-15/kgrp1
    const uint32_t aLdOff = (uint32_t)(((wm * 64 + (lane & 15)) * TILE_ROW_F
                                        + (lane >> 4) * 4) * 4);
    // B .x2: lanes 0-7 rows 0-7/kgrp0, lanes 8-15 rows 0-7/kgrp1 (lanes 16+ unused)
    const uint32_t bLdOff = (uint32_t)(((wn * 32 + (lane & 7)) * TILE_ROW_F
                                        + ((lane >> 3) & 1) * 4) * 4);
    const uint32_t aSmemBase = smem_u32(Asm);
    const uint32_t bSmemBase = smem_u32(Bsm);

    int rs = 0;
    for (int kt = 0; kt < KT; kt++) {
        CP_WAIT1();
        __syncthreads();

        const int kp = kt + 2;
        if (kp < KT) {
            const int k0 = kp << 5;
            const int s  = kp % 3;
            const uint32_t ao = (uint32_t)s * (A_STAGE_F * 4);
            const uint32_t bo = (uint32_t)s * (B_STAGE_F * 4);
            #pragma unroll
            for (int it = 0; it < 4; it++) {
                CP_ASYNC16(sAb + ao + it * rowStep, aSrc[it] + k0);
                CP_ASYNC16(sBb + bo + it * rowStep, bSrc[it] + k0);
            }
        }
        CP_COMMIT();

        const uint32_t aS = aSmemBase + (uint32_t)rs * (A_STAGE_F * 4) + aLdOff;
        const uint32_t bS = bSmemBase + (uint32_t)rs * (B_STAGE_F * 4) + bLdOff;
        #pragma unroll
        for (int ks = 0; ks < 4; ks++) {
            uint32_t a[4][4], b[4][2];
            #pragma unroll
            for (int mt = 0; mt < 4; mt++)
                LDSM4(a[mt][0], a[mt][1], a[mt][2], a[mt][3],
                      aS + (uint32_t)((mt * 16 * TILE_ROW_F + ks * 8) * 4));
            #pragma unroll
            for (int nt = 0; nt < 4; nt++)
                LDSM2(b[nt][0], b[nt][1],
                      bS + (uint32_t)((nt * 8 * TILE_ROW_F + ks * 8) * 4));
            #pragma unroll
            for (int mt = 0; mt < 4; mt++)
                #pragma unroll
                for (int nt = 0; nt < 4; nt++)
                    mma_tf32(acc[mt][nt], a[mt], b[nt]);
        }
        rs++; if (rs == 3) rs = 0;
    }

    // ---- epilogue
    #pragma unroll
    for (int mt = 0; mt < 4; mt++) {
        #pragma unroll
        for (int h2 = 0; h2 < 2; h2++) {
            const int m = m0 + wm * 64 + mt * 16 + q + h2 * 8;
            if (m >= Me) continue;
            float* crow = Ce + (size_t)m * N + n0 + wn * 32;
            float rsw = 1.f;
            if (EPI == 4) rsw = rowscale[e * NTOK + m];
            #pragma unroll
            for (int nt = 0; nt < 4; nt++) {
                const int col = nt * 8 + 2 * r;
                float v0 = acc[mt][nt][h2 * 2 + 0];
                float v1 = acc[mt][nt][h2 * 2 + 1];
                if (EPI == 1 || EPI == 2) {
                    const float2 bb = *(const float2*)(bias + n0 + wn * 32 + col);
                    v0 += bb.x; v1 += bb.y;
                }
                if (EPI == 2) {
                    const float2 rr = *(const float2*)(res + (size_t)m * N + n0 + wn * 32 + col);
                    v0 += rr.x; v1 += rr.y;
                }
                if (EPI == 3) {
                    const float2 hh = *(const float2*)(other + (size_t)e * strideCe
                                                       + (size_t)m * N + n0 + wn * 32 + col);
                    v0 = (hh.x / (1.f + __expf(-hh.x))) * v0;
                    v1 = (hh.y / (1.f + __expf(-hh.y))) * v1;
                }
                if (EPI == 4) { v0 *= rsw; v1 *= rsw; }
                *(float2*)(crow + col) = make_float2(v0, v1);
            }
        }
    }
}

// ---------------- Flash attention (fp32x2 packed FFMA2, online softmax) -------
// grid: (S/128, B*H), 128 threads; each thread owns one query row.
#define FA_SMEM ((64*64 + 64*64 + 128*65) * 4)
__global__ __launch_bounds__(128) void flash_attn_kernel(
    const float* __restrict__ qkv, float* __restrict__ out)
{
    extern __shared__ float sh[];
    float* Ks = sh;
    float* Vs = sh + 64*64;
    float* Ss = sh + 2*64*64;

    const int tid = threadIdx.x;
    const int b   = blockIdx.y & 1;
    const int h   = blockIdx.y >> 1;
    const int s_q = blockIdx.x * 128 + tid;

    const size_t qbase = ((size_t)(s_q * BATCH + b)) * (3*DMODEL) + h * DHEAD;
    ull_t q2[32];
    #pragma unroll
    for (int d = 0; d < 64; d += 4) {
        float4 v = *(const float4*)(qkv + qbase + d);
        q2[d/2]     = pk2(v.x * 0.125f, v.y * 0.125f);
        q2[d/2 + 1] = pk2(v.z * 0.125f, v.w * 0.125f);
    }
    ull_t o2[32];
    #pragma unroll
    for (int d = 0; d < 32; d++) o2[d] = 0ull;
    float mrow = -1e30f, lrow = 0.f;

    for (int kt = 0; kt < S_LEN; kt += 64) {
        __syncthreads();
        for (int idx = tid; idx < 64*16; idx += 128) {
            const int rr = idx >> 4, c = (idx & 15) * 4;
            const size_t base = ((size_t)((kt + rr) * BATCH + b)) * (3*DMODEL) + h * DHEAD + c;
            *(float4*)(Ks + rr*64 + c) = *(const float4*)(qkv + DMODEL   + base);
            *(float4*)(Vs + rr*64 + c) = *(const float4*)(qkv + 2*DMODEL + base);
        }
        __syncthreads();

        // pass 1: scores s_j = q . k_j  (packed f32x2, 4 rotating accumulators)
        float mt = -1e30f;
        for (int j = 0; j < 64; j++) {
            const ulonglong2* kr = (const ulonglong2*)(Ks + j*64);
            ull_t a0 = 0ull, a1 = 0ull, a2 = 0ull, a3 = 0ull;
            #pragma unroll
            for (int i = 0; i < 8; i++) {
                ulonglong2 k0 = kr[2*i], k1 = kr[2*i + 1];
                FMA2(a0, q2[4*i    ], k0.x);
                FMA2(a1, q2[4*i + 1], k0.y);
                FMA2(a2, q2[4*i + 2], k1.x);
                FMA2(a3, q2[4*i + 3], k1.y);
            }
            ADD2(a0, a0, a1); ADD2(a2, a2, a3); ADD2(a0, a0, a2);
            float lo, hi; upk2(lo, hi, a0);
            const float s = lo + hi;
            Ss[tid*65 + j] = s;
            mt = fmaxf(mt, s);
        }

        const float mnew = fmaxf(mrow, mt);
        const float corr = __expf(mrow - mnew);
        lrow *= corr;
        {
            const ull_t pc = pk2(corr, corr);
            #pragma unroll
            for (int d = 0; d < 32; d++) { ull_t t = o2[d]; MUL2(o2[d], t, pc); }
        }

        // pass 2: o += p_j * v_j  (packed, 32 independent accumulators)
        for (int j = 0; j < 64; j++) {
            const float p = __expf(Ss[tid*65 + j] - mnew);
            lrow += p;
            const ull_t pp = pk2(p, p);
            const ulonglong2* vr = (const ulonglong2*)(Vs + j*64);
            #pragma unroll
            for (int i = 0; i < 16; i++) {
                ulonglong2 vv = vr[i];
                FMA2(o2[2*i    ], pp, vv.x);
                FMA2(o2[2*i + 1], pp, vv.y);
            }
        }
        mrow = mnew;
    }
    const float inv = 1.f / lrow;
    const size_t obase = ((size_t)(s_q * BATCH + b)) * DMODEL + h * DHEAD;
    #pragma unroll
    for (int d = 0; d < 64; d += 4) {
        float x0, x1, x2, x3;
        upk2(x0, x1, o2[d/2]);
        upk2(x2, x3, o2[d/2 + 1]);
        *(float4*)(out + obase + d) = make_float4(x0*inv, x1*inv, x2*inv, x3*inv);
    }
}

// ---------------- Router -------------------------------------------------------
__global__ void zero_cnt_kernel(int* cnt) { if (threadIdx.x < NEXP) cnt[threadIdx.x] = 0; }

__global__ __launch_bounds__(256) void router_kernel(
    const float* __restrict__ h, const float* __restrict__ gw,
    float* __restrict__ logits_out,
    int* __restrict__ rows, float* __restrict__ rwgt,
    int* __restrict__ trow, int* __restrict__ cnt)
{
    const int warp = threadIdx.x >> 5, lane = threadIdx.x & 31;
    const int t = blockIdx.x * 8 + warp;
    const float* hr = h + (size_t)t * DMODEL;
    float lg[NEXP];
    #pragma unroll
    for (int e = 0; e < NEXP; e++) {
        const float* gr = gw + e * DMODEL;
        float p = 0.f;
        for (int i = lane; i < DMODEL; i += 32) p += hr[i] * gr[i];
        #pragma unroll
        for (int off = 16; off; off >>= 1) p += __shfl_xor_sync(0xffffffffu, p, off);
        lg[e] = p;
    }
    if (lane == 0) {
        if (logits_out) {
            #pragma unroll
            for (int e = 0; e < NEXP; e++) logits_out[(size_t)t * NEXP + e] = lg[e];
        }
        float mx = lg[0];
        #pragma unroll
        for (int e = 1; e < NEXP; e++) mx = fmaxf(mx, lg[e]);
        float pr[NEXP];
        #pragma unroll
        for (int e = 0; e < NEXP; e++) pr[e] = __expf(lg[e] - mx);
        int i0 = 0;
        #pragma unroll
        for (int e = 1; e < NEXP; e++) if (pr[e] > pr[i0]) i0 = e;
        int i1 = (i0 == 0) ? 1 : 0;
        #pragma unroll
        for (int e = 0; e < NEXP; e++) if (e != i0 && pr[e] > pr[i1]) i1 = e;
        const float ws = pr[i0] + pr[i1];
        const float w0 = pr[i0] / ws, w1 = pr[i1] / ws;
        int p0 = atomicAdd(&cnt[i0], 1);
        rows[i0*NTOK + p0] = t; rwgt[i0*NTOK + p0] = w0; trow[2*t + 0] = i0*NTOK + p0;
        int p1 = atomicAdd(&cnt[i1], 1);
        rows[i1*NTOK + p1] = t; rwgt[i1*NTOK + p1] = w1; trow[2*t + 1] = i1*NTOK + p1;
    }
}

// ---------------- Final combine ------------------------------------------------
__global__ __launch_bounds__(256) void combine_kernel(
    const float* __restrict__ x2, const float* __restrict__ y,
    const int* __restrict__ trow, float* __restrict__ out)
{
    const int t = blockIdx.x;
    const int r0 = trow[2*t], r1 = trow[2*t + 1];
    const int i = threadIdx.x * 4;
    float4 a  = *(const float4*)(x2 + (size_t)t  * DMODEL + i);
    float4 y0 = *(const float4*)(y  + (size_t)r0 * DMODEL + i);
    float4 y1 = *(const float4*)(y  + (size_t)r1 * DMODEL + i);
    float4 o = make_float4(a.x + y0.x + y1.x, a.y + y0.y + y1.y,
                           a.z + y0.z + y1.z, a.w + y0.w + y1.w);
    *(float4*)(out + (size_t)t * DMODEL + i) = o;
}

// ---------------- host orchestration ------------------------------------------
extern "C" void kernel_launch(void* const* d_in, const int* in_sizes, int n_in,
                              void* d_out, int out_size)
{
    const float* x        = (const float*)d_in[0];
    const float* inproj_w = (const float*)d_in[1];
    const float* inproj_b = (const float*)d_in[2];
    const float* outproj_w= (const float*)d_in[3];
    const float* outproj_b= (const float*)d_in[4];
    const float* ln1_g    = (const float*)d_in[5];
    const float* ln1_b    = (const float*)d_in[6];
    const float* ln2_g    = (const float*)d_in[7];
    const float* ln2_b    = (const float*)d_in[8];
    const float* gate_w   = (const float*)d_in[9];
    const float* w1       = (const float*)d_in[10];
    const float* w2       = (const float*)d_in[11];
    const float* w3       = (const float*)d_in[12];

    float* out = (float*)d_out;
    float* logits_out = (out_size > NTOK * DMODEL) ? out + (size_t)NTOK * DMODEL : nullptr;

    float *p_ln1, *p_qkv, *p_attn, *p_x2, *p_ln2, *p_h1, *p_y, *p_rwgt;
    int *p_rows, *p_trow, *p_cnt;
    cudaGetSymbolAddress((void**)&p_ln1,  g_ln1);
    cudaGetSymbolAddress((void**)&p_qkv,  g_qkv);
    cudaGetSymbolAddress((void**)&p_attn, g_attn);
    cudaGetSymbolAddress((void**)&p_x2,   g_x2);
    cudaGetSymbolAddress((void**)&p_ln2,  g_ln2);
    cudaGetSymbolAddress((void**)&p_h1,   g_h1);
    cudaGetSymbolAddress((void**)&p_y,    g_y);
    cudaGetSymbolAddress((void**)&p_rwgt, g_rwgt);
    cudaGetSymbolAddress((void**)&p_rows, g_rows);
    cudaGetSymbolAddress((void**)&p_trow, g_trow);
    cudaGetSymbolAddress((void**)&p_cnt,  g_cnt);

    cudaFuncSetAttribute(gemm_tf32<1,false,false>, cudaFuncAttributeMaxDynamicSharedMemorySize, GEMM_SMEM);
    cudaFuncSetAttribute(gemm_tf32<2,false,false>, cudaFuncAttributeMaxDynamicSharedMemorySize, GEMM_SMEM);
    cudaFuncSetAttribute(gemm_tf32<0,true, true >, cudaFuncAttributeMaxDynamicSharedMemorySize, GEMM_SMEM);
    cudaFuncSetAttribute(gemm_tf32<3,true, true >, cudaFuncAttributeMaxDynamicSharedMemorySize, GEMM_SMEM);
    cudaFuncSetAttribute(gemm_tf32<4,false,true >, cudaFuncAttributeMaxDynamicSharedMemorySize, GEMM_SMEM);
    cudaFuncSetAttribute(flash_attn_kernel,        cudaFuncAttributeMaxDynamicSharedMemorySize, FA_SMEM);

    // 1. LN1
    ln_kernel<<<NTOK, 256>>>(x, ln1_g, ln1_b, p_ln1);

    // 2. QKV = ln1 @ W_in^T + b   [4096, 3072]
    gemm_tf32<1,false,false><<<dim3(3*DMODEL/128, NTOK/128), 256, GEMM_SMEM>>>(
        p_ln1, inproj_w, p_qkv, inproj_b, nullptr, nullptr, nullptr, nullptr, nullptr,
        NTOK, 3*DMODEL, DMODEL, 0, 0, 0);

    // 3. Flash attention
    flash_attn_kernel<<<dim3(S_LEN/128, BATCH*NHEAD), 128, FA_SMEM>>>(p_qkv, p_attn);

    // 4. x2 = x + attn @ W_out^T + b
    gemm_tf32<2,false,false><<<dim3(DMODEL/128, NTOK/128), 256, GEMM_SMEM>>>(
        p_attn, outproj_w, p_x2, outproj_b, x, nullptr, nullptr, nullptr, nullptr,
        NTOK, DMODEL, DMODEL, 0, 0, 0);

    // 5. LN2
    ln_kernel<<<NTOK, 256>>>(p_x2, ln2_g, ln2_b, p_ln2);

    // 6. Router
    zero_cnt_kernel<<<1, 32>>>(p_cnt);
    router_kernel<<<NTOK/8, 256>>>(p_ln2, gate_w, logits_out,
                                   p_rows, p_rwgt, p_trow, p_cnt);

    // 7. MoE expert GEMMs (grouped, gathered)
    gemm_tf32<0,true,true><<<dim3(FFN_DIM/128, NTOK/128, NEXP), 256, GEMM_SMEM>>>(
        p_ln2, w1, p_h1, nullptr, nullptr, nullptr, nullptr, p_rows, p_cnt,
        NTOK, FFN_DIM, DMODEL,
        0, (size_t)FFN_DIM*DMODEL, (size_t)NTOK*FFN_DIM);
    gemm_tf32<3,true,true><<<dim3(FFN_DIM/128, NTOK/128, NEXP), 256, GEMM_SMEM>>>(
        p_ln2, w3, p_h1, nullptr, nullptr, p_h1, nullptr, p_rows, p_cnt,
        NTOK, FFN_DIM, DMODEL,
        0, (size_t)FFN_DIM*DMODEL, (size_t)NTOK*FFN_DIM);
    gemm_tf32<4,false,true><<<dim3(DMODEL/128, NTOK/128, NEXP), 256, GEMM_SMEM>>>(
        p_h1, w2, p_y, nullptr, nullptr, nullptr, p_rwgt, nullptr, p_cnt,
        NTOK, DMODEL, FFN_DIM,
        (size_t)NTOK*FFN_DIM, (size_t)DMODEL*FFN_DIM, (size_t)NTOK*DMODEL);

    // 8. out = x2 + Y[slot0] + Y[slot1]
    combine_kernel<<<NTOK, 256>>>(p_x2, p_y, p_trow, out);
}

// round 14
// speedup vs baseline: 1.8892x; 1.5353x over previous
#include <cuda_runtime.h>
#include <cstddef>
#include <cstdint>

// Problem constants
#define S_LEN   2048
#define BATCH   2
#define DMODEL  1024
#define NHEAD   16
#define DHEAD   64
#define FFN_DIM 4096
#define NEXP    8
#define NTOK    (S_LEN*BATCH)          // 4096 tokens, t = s*BATCH + b

// ---------------- scratch (static device globals; no runtime allocation) ----
__device__ float g_ln1 [(size_t)NTOK*DMODEL];
__device__ float g_qkv [(size_t)NTOK*3*DMODEL];
__device__ float g_attn[(size_t)NTOK*DMODEL];
__device__ float g_x2  [(size_t)NTOK*DMODEL];
__device__ float g_ln2 [(size_t)NTOK*DMODEL];
__device__ float g_h1  [(size_t)NEXP*NTOK*FFN_DIM];   // expert hidden
__device__ float g_y   [(size_t)NEXP*NTOK*DMODEL];    // expert outputs
__device__ int   g_rows[NEXP*NTOK];
__device__ float g_rwgt[NEXP*NTOK];
__device__ int   g_trow[2*NTOK];
__device__ int   g_cnt [NEXP];

// ---------------- helpers ----------------------------------------------------
__device__ __forceinline__ uint32_t smem_u32(const void* p) {
    return (uint32_t)__cvta_generic_to_shared(p);
}
#define CP_ASYNC16(dst, src) \
    asm volatile("cp.async.cg.shared.global [%0], [%1], 16;\n" :: "r"(dst), "l"(src))
#define CP_COMMIT()  asm volatile("cp.async.commit_group;\n")
#define CP_WAIT1()   asm volatile("cp.async.wait_group 1;\n")

#define LDSM4(r0, r1, r2, r3, addr) \
    asm volatile("ldmatrix.sync.aligned.m8n8.x4.shared.b16 {%0,%1,%2,%3}, [%4];" \
        : "=r"(r0), "=r"(r1), "=r"(r2), "=r"(r3) : "r"(addr))
#define LDSM2(r0, r1, addr) \
    asm volatile("ldmatrix.sync.aligned.m8n8.x2.shared.b16 {%0,%1}, [%2];" \
        : "=r"(r0), "=r"(r1) : "r"(addr))

__device__ __forceinline__ void mma_tf32(float c[4], const uint32_t a[4], const uint32_t b[2]) {
    asm volatile(
        "mma.sync.aligned.m16n8k8.row.col.f32.tf32.tf32.f32 "
        "{%0,%1,%2,%3}, {%4,%5,%6,%7}, {%8,%9}, {%0,%1,%2,%3};"
        : "+f"(c[0]), "+f"(c[1]), "+f"(c[2]), "+f"(c[3])
        : "r"(a[0]), "r"(a[1]), "r"(a[2]), "r"(a[3]), "r"(b[0]), "r"(b[1]));
}

// ---------------- LayerNorm: one block per token row --------------------------
__global__ __launch_bounds__(256) void ln_kernel(
    const float* __restrict__ x, const float* __restrict__ g,
    const float* __restrict__ b, float* __restrict__ y)
{
    const int t   = blockIdx.x;
    const int tid = threadIdx.x;
    const float* xr = x + (size_t)t * DMODEL;
    float4 v = *(const float4*)(xr + tid * 4);
    float s  = v.x + v.y + v.z + v.w;
    float s2 = v.x*v.x + v.y*v.y + v.z*v.z + v.w*v.w;
    __shared__ float red[64];
    const int lane = tid & 31, wid = tid >> 5;
    #pragma unroll
    for (int off = 16; off; off >>= 1) {
        s  += __shfl_down_sync(0xffffffffu, s,  off);
        s2 += __shfl_down_sync(0xffffffffu, s2, off);
    }
    if (lane == 0) { red[wid] = s; red[32 + wid] = s2; }
    __syncthreads();
    if (tid == 0) {
        float ts = 0.f, ts2 = 0.f;
        #pragma unroll
        for (int i = 0; i < 8; i++) { ts += red[i]; ts2 += red[32 + i]; }
        float mean = ts * (1.f / DMODEL);
        float var  = ts2 * (1.f / DMODEL) - mean * mean;
        red[16] = mean;
        red[17] = rsqrtf(var + 1e-5f);
    }
    __syncthreads();
    const float mean = red[16], rstd = red[17];
    float4 gg = *(const float4*)(g + tid * 4);
    float4 bb = *(const float4*)(b + tid * 4);
    float4 o;
    o.x = (v.x - mean) * rstd * gg.x + bb.x;
    o.y = (v.y - mean) * rstd * gg.y + bb.y;
    o.z = (v.z - mean) * rstd * gg.z + bb.z;
    o.w = (v.w - mean) * rstd * gg.w + bb.w;
    *(float4*)(y + (size_t)t * DMODEL + tid * 4) = o;
}

// ---------------- TF32 tensor-core GEMM (128x128 tile, BK=32, ldmatrix) -------
// (unchanged from the 3177us winner)
#define TILE_ROW_F 36
#define A_STAGE_F  (128 * TILE_ROW_F)
#define B_STAGE_F  (128 * TILE_ROW_F)
#define GEMM_SMEM  (3 * (A_STAGE_F + B_STAGE_F) * 4)

template<int EPI, bool GATHER, bool GROUPED>
__global__ __launch_bounds__(256, 2) void gemm_tf32(
    const float* __restrict__ A, const float* __restrict__ Bw, float* __restrict__ C,
    const float* __restrict__ bias, const float* __restrict__ res,
    const float* __restrict__ other, const float* __restrict__ rowscale,
    const int* __restrict__ rowsIdx, const int* __restrict__ cnt,
    int M, int N, int K,
    size_t strideAe, size_t strideBe, size_t strideCe)
{
    const int e  = GROUPED ? blockIdx.z : 0;
    int Me = M;
    if (GROUPED && cnt) Me = cnt[e];
    const int m0 = blockIdx.y * 128;
    if (m0 >= Me) return;
    const int n0 = blockIdx.x * 128;

    const float* Ae = A  + (size_t)e * strideAe;
    const float* Be = Bw + (size_t)e * strideBe;
    float*       Ce = C  + (size_t)e * strideCe;

    extern __shared__ float sh[];
    float* Asm = sh;
    float* Bsm = sh + 3 * A_STAGE_F;

    const int tid  = threadIdx.x;
    const int lane = tid & 31, wid = tid >> 5;
    const int wm = wid >> 2, wn = wid & 3;
    const int q  = lane >> 2, r = lane & 3;

    const int ldRow0 = tid >> 3;
    const int seg    = tid & 7;
    const float* aSrc[4];
    const float* bSrc[4];
    #pragma unroll
    for (int it = 0; it < 4; it++) {
        int am = m0 + ldRow0 + it * 32;
        if (am >= Me) am = Me - 1;
        const size_t ar = GATHER ? (size_t)rowsIdx[e * NTOK + am] : (size_t)am;
        aSrc[it] = Ae + ar * K + seg * 4;
        bSrc[it] = Be + (size_t)(n0 + ldRow0 + it * 32) * K + seg * 4;
    }
    const uint32_t sAb = smem_u32(Asm) + (uint32_t)(ldRow0 * TILE_ROW_F + seg * 4) * 4;
    const uint32_t sBb = smem_u32(Bsm) + (uint32_t)(ldRow0 * TILE_ROW_F + seg * 4) * 4;
    const uint32_t rowStep = 32 * TILE_ROW_F * 4;

    const int KT = K >> 5;

    #pragma unroll
    for (int s = 0; s < 2; s++) {
        const int k0 = s << 5;
        const uint32_t ao = s * (A_STAGE_F * 4);
        const uint32_t bo = s * (B_STAGE_F * 4);
        #pragma unroll
        for (int it = 0; it < 4; it++) {
            CP_ASYNC16(sAb + ao + it * rowStep, aSrc[it] + k0);
            CP_ASYNC16(sBb + bo + it * rowStep, bSrc[it] + k0);
        }
        CP_COMMIT();
    }

    float acc[4][4][4];
    #pragma unroll
    for (int i = 0; i < 4; i++)
        #pragma unroll
        for (int j = 0; j < 4; j++)
            #pragma unroll
            for (int k = 0; k < 4; k++) acc[i][j][k] = 0.f;

    const uint32_t aLdOff = (uint32_t)(((wm * 64 + (lane & 15)) * TILE_ROW_F
                                        + (lane >> 4) * 4) * 4);
    const uint32_t bLdOff = (uint32_t)(((wn * 32 + (lane & 7)) * TILE_ROW_F
                                        + ((lane >> 3) & 1) * 4) * 4);
    const uint32_t aSmemBase = smem_u32(Asm);
    const uint32_t bSmemBase = smem_u32(Bsm);

    int rs = 0;
    for (int kt = 0; kt < KT; kt++) {
        CP_WAIT1();
        __syncthreads();

        const int kp = kt + 2;
        if (kp < KT) {
            const int k0 = kp << 5;
            const int s  = kp % 3;
            const uint32_t ao = (uint32_t)s * (A_STAGE_F * 4);
            const uint32_t bo = (uint32_t)s * (B_STAGE_F * 4);
            #pragma unroll
            for (int it = 0; it < 4; it++) {
                CP_ASYNC16(sAb + ao + it * rowStep, aSrc[it] + k0);
                CP_ASYNC16(sBb + bo + it * rowStep, bSrc[it] + k0);
            }
        }
        CP_COMMIT();

        const uint32_t aS = aSmemBase + (uint32_t)rs * (A_STAGE_F * 4) + aLdOff;
        const uint32_t bS = bSmemBase + (uint32_t)rs * (B_STAGE_F * 4) + bLdOff;
        #pragma unroll
        for (int ks = 0; ks < 4; ks++) {
            uint32_t a[4][4], b[4][2];
            #pragma unroll
            for (int mt = 0; mt < 4; mt++)
                LDSM4(a[mt][0], a[mt][1], a[mt][2], a[mt][3],
                      aS + (uint32_t)((mt * 16 * TILE_ROW_F + ks * 8) * 4));
            #pragma unroll
            for (int nt = 0; nt < 4; nt++)
                LDSM2(b[nt][0], b[nt][1],
                      bS + (uint32_t)((nt * 8 * TILE_ROW_F + ks * 8) * 4));
            #pragma unroll
            for (int mt = 0; mt < 4; mt++)
                #pragma unroll
                for (int nt = 0; nt < 4; nt++)
                    mma_tf32(acc[mt][nt], a[mt], b[nt]);
        }
        rs++; if (rs == 3) rs = 0;
    }

    #pragma unroll
    for (int mt = 0; mt < 4; mt++) {
        #pragma unroll
        for (int h2 = 0; h2 < 2; h2++) {
            const int m = m0 + wm * 64 + mt * 16 + q + h2 * 8;
            if (m >= Me) continue;
            float* crow = Ce + (size_t)m * N + n0 + wn * 32;
            float rsw = 1.f;
            if (EPI == 4) rsw = rowscale[e * NTOK + m];
            #pragma unroll
            for (int nt = 0; nt < 4; nt++) {
                const int col = nt * 8 + 2 * r;
                float v0 = acc[mt][nt][h2 * 2 + 0];
                float v1 = acc[mt][nt][h2 * 2 + 1];
                if (EPI == 1 || EPI == 2) {
                    const float2 bb = *(const float2*)(bias + n0 + wn * 32 + col);
                    v0 += bb.x; v1 += bb.y;
                }
                if (EPI == 2) {
                    const float2 rr = *(const float2*)(res + (size_t)m * N + n0 + wn * 32 + col);
                    v0 += rr.x; v1 += rr.y;
                }
                if (EPI == 3) {
                    const float2 hh = *(const float2*)(other + (size_t)e * strideCe
                                                       + (size_t)m * N + n0 + wn * 32 + col);
                    v0 = (hh.x / (1.f + __expf(-hh.x))) * v0;
                    v1 = (hh.y / (1.f + __expf(-hh.y))) * v1;
                }
                if (EPI == 4) { v0 *= rsw; v1 *= rsw; }
                *(float2*)(crow + col) = make_float2(v0, v1);
            }
        }
    }
}

// ---------------- Flash attention via tf32 tensor cores -----------------------
// grid (S/128, B*H), 256 threads = 8 warps; warp w owns q rows w*16..w*16+15.
// KV tiles of 64. K staged transposed Kt[dh][kv] (stride 72), V natural [kv][72].
// Scores/O live in m16n8k8 fragments; softmax on frags (quad shuffles);
// P -> A-frag via per-warp smem round trip (warp-private rows of the Q buffer).
#define FA_STRIDE 72
#define FA2_SMEM  ((2 * 64 * FA_STRIDE + 128 * FA_STRIDE) * 4)   // Kt + V + Q/P

__global__ __launch_bounds__(256) void flash_attn_mma(
    const float* __restrict__ qkv, float* __restrict__ out)
{
    extern __shared__ float sh[];
    float* Kt = sh;                         // [64 dh][FA_STRIDE] over kv
    float* Vs = sh + 64 * FA_STRIDE;        // [64 kv][FA_STRIDE] over dh
    float* Qs = sh + 2 * 64 * FA_STRIDE;    // [128][FA_STRIDE]; reused as P (warp-private rows)

    const int tid  = threadIdx.x;
    const int lane = tid & 31, wid = tid >> 5;
    const int q = lane >> 2, r = lane & 3;
    const int b = blockIdx.y & 1;
    const int h = blockIdx.y >> 1;
    const int q0 = blockIdx.x * 128;

    // ---- stage Q (scaled by 1/sqrt(64) = 0.125)
    for (int chunk = tid; chunk < 128 * 16; chunk += 256) {
        const int row = chunk >> 4, c4 = (chunk & 15) * 4;
        const size_t tok = (size_t)(q0 + row) * BATCH + b;
        float4 v = *(const float4*)(qkv + tok * (3*DMODEL) + h * DHEAD + c4);
        v.x *= 0.125f; v.y *= 0.125f; v.z *= 0.125f; v.w *= 0.125f;
        *(float4*)(Qs + row * FA_STRIDE + c4) = v;
    }
    __syncthreads();

    // ---- Q A-fragments (register resident, 8 k-chunks x 4)
    uint32_t qf[8][4];
    {
        const float* qw = Qs + (wid * 16) * FA_STRIDE;
        #pragma unroll
        for (int kj = 0; kj < 8; kj++) {
            qf[kj][0] = __float_as_uint(qw[(q    ) * FA_STRIDE + 8*kj + r    ]);
            qf[kj][1] = __float_as_uint(qw[(q + 8) * FA_STRIDE + 8*kj + r    ]);
            qf[kj][2] = __float_as_uint(qw[(q    ) * FA_STRIDE + 8*kj + r + 4]);
            qf[kj][3] = __float_as_uint(qw[(q + 8) * FA_STRIDE + 8*kj + r + 4]);
        }
    }
    // warp-private P region = same rows; only this warp touches them from here on.

    float m0v = -1e30f, m1v = -1e30f, l0 = 0.f, l1 = 0.f;
    float o[8][4];
    #pragma unroll
    for (int nj = 0; nj < 8; nj++)
        #pragma unroll
        for (int i = 0; i < 4; i++) o[nj][i] = 0.f;

    float* Pw = Qs + (wid * 16) * FA_STRIDE;

    for (int kt = 0; kt < S_LEN; kt += 64) {
        __syncthreads();   // prior tile's Kt/Vs reads done before overwrite

        // stage K transposed: warp w covers dh cols w*8..w*8+7; kv = lane (2 rounds)
        #pragma unroll
        for (int rep = 0; rep < 2; rep++) {
            const int kv = rep * 32 + lane;
            const size_t tok = (size_t)(kt + kv) * BATCH + b;
            const float* kp = qkv + tok * (3*DMODEL) + DMODEL + h * DHEAD + wid * 8;
            const float4 k0 = *(const float4*)(kp);
            const float4 k1 = *(const float4*)(kp + 4);
            Kt[(wid*8 + 0) * FA_STRIDE + kv] = k0.x;
            Kt[(wid*8 + 1) * FA_STRIDE + kv] = k0.y;
            Kt[(wid*8 + 2) * FA_STRIDE + kv] = k0.z;
            Kt[(wid*8 + 3) * FA_STRIDE + kv] = k0.w;
            Kt[(wid*8 + 4) * FA_STRIDE + kv] = k1.x;
            Kt[(wid*8 + 5) * FA_STRIDE + kv] = k1.y;
            Kt[(wid*8 + 6) * FA_STRIDE + kv] = k1.z;
            Kt[(wid*8 + 7) * FA_STRIDE + kv] = k1.w;
        }
        // stage V natural
        for (int chunk = tid; chunk < 64 * 16; chunk += 256) {
            const int row = chunk >> 4, c4 = (chunk & 15) * 4;
            const size_t tok = (size_t)(kt + row) * BATCH + b;
            *(float4*)(Vs + row * FA_STRIDE + c4) =
                *(const float4*)(qkv + tok * (3*DMODEL) + 2*DMODEL + h * DHEAD + c4);
        }
        __syncthreads();

        // ---- scores S = Q @ K^T   (8 n-frags of 8 kv cols each)
        float sc[8][4];
        #pragma unroll
        for (int nj = 0; nj < 8; nj++)
            #pragma unroll
            for (int i = 0; i < 4; i++) sc[nj][i] = 0.f;
        #pragma unroll
        for (int kj = 0; kj < 8; kj++) {
            uint32_t bf[8][2];
            #pragma unroll
            for (int nj = 0; nj < 8; nj++) {
                bf[nj][0] = __float_as_uint(Kt[(8*kj + r    ) * FA_STRIDE + 8*nj + q]);
                bf[nj][1] = __float_as_uint(Kt[(8*kj + r + 4) * FA_STRIDE + 8*nj + q]);
            }
            #pragma unroll
            for (int nj = 0; nj < 8; nj++)
                mma_tf32(sc[nj], qf[kj], bf[nj]);
        }

        // ---- online softmax on fragments (rows q and q+8)
        float mt0 = -1e30f, mt1 = -1e30f;
        #pragma unroll
        for (int nj = 0; nj < 8; nj++) {
            mt0 = fmaxf(mt0, fmaxf(sc[nj][0], sc[nj][1]));
            mt1 = fmaxf(mt1, fmaxf(sc[nj][2], sc[nj][3]));
        }
        mt0 = fmaxf(mt0, __shfl_xor_sync(0xffffffffu, mt0, 1));
        mt0 = fmaxf(mt0, __shfl_xor_sync(0xffffffffu, mt0, 2));
        mt1 = fmaxf(mt1, __shfl_xor_sync(0xffffffffu, mt1, 1));
        mt1 = fmaxf(mt1, __shfl_xor_sync(0xffffffffu, mt1, 2));

        const float mn0 = fmaxf(m0v, mt0), mn1 = fmaxf(m1v, mt1);
        const float c0 = __expf(m0v - mn0), c1 = __expf(m1v - mn1);
        float s0 = 0.f, s1 = 0.f;
        #pragma unroll
        for (int nj = 0; nj < 8; nj++) {
            float p0 = __expf(sc[nj][0] - mn0);
            float p1 = __expf(sc[nj][1] - mn0);
            float p2 = __expf(sc[nj][2] - mn1);
            float p3 = __expf(sc[nj][3] - mn1);
            sc[nj][0] = p0; sc[nj][1] = p1; sc[nj][2] = p2; sc[nj][3] = p3;
            s0 += p0 + p1; s1 += p2 + p3;
        }
        s0 += __shfl_xor_sync(0xffffffffu, s0, 1);
        s0 += __shfl_xor_sync(0xffffffffu, s0, 2);
        s1 += __shfl_xor_sync(0xffffffffu, s1, 1);
        s1 += __shfl_xor_sync(0xffffffffu, s1, 2);
        l0 = l0 * c0 + s0;
        l1 = l1 * c1 + s1;
        #pragma unroll
        for (int nj = 0; nj < 8; nj++) {
            o[nj][0] *= c0; o[nj][1] *= c0;
            o[nj][2] *= c1; o[nj][3] *= c1;
        }
        m0v = mn0; m1v = mn1;

        // ---- P -> warp-private smem -> A-fragments
        __syncwarp();   // prior PV A-frag loads done before overwrite
        #pragma unroll
        for (int nj = 0; nj < 8; nj++) {
            *(float2*)(Pw + (q    ) * FA_STRIDE + 8*nj + 2*r) = make_float2(sc[nj][0], sc[nj][1]);
            *(float2*)(Pw + (q + 8) * FA_STRIDE + 8*nj + 2*r) = make_float2(sc[nj][2], sc[nj][3]);
        }
        __syncwarp();

        // ---- O += P @ V
        #pragma unroll
        for (int kj = 0; kj < 8; kj++) {
            uint32_t pa[4];
            pa[0] = __float_as_uint(Pw[(q    ) * FA_STRIDE + 8*kj + r    ]);
            pa[1] = __float_as_uint(Pw[(q + 8) * FA_STRIDE + 8*kj + r    ]);
            pa[2] = __float_as_uint(Pw[(q    ) * FA_STRIDE + 8*kj + r + 4]);
            pa[3] = __float_as_uint(Pw[(q + 8) * FA_STRIDE + 8*kj + r + 4]);
            #pragma unroll
            for (int nj = 0; nj < 8; nj++) {
                uint32_t vb[2];
                vb[0] = __float_as_uint(Vs[(8*kj + r    ) * FA_STRIDE + 8*nj + q]);
                vb[1] = __float_as_uint(Vs[(8*kj + r + 4) * FA_STRIDE + 8*nj + q]);
                mma_tf32(o[nj], pa, vb);
            }
        }
    }

    // ---- epilogue
    const float inv0 = 1.f / l0, inv1 = 1.f / l1;
    const int row0 = q0 + wid * 16 + q;
    #pragma unroll
    for (int nj = 0; nj < 8; nj++) {
        const int col = h * DHEAD + 8*nj + 2*r;
        *(float2*)(out + ((size_t)row0 * BATCH + b) * DMODEL + col) =
            make_float2(o[nj][0] * inv0, o[nj][1] * inv0);
        *(float2*)(out + ((size_t)(row0 + 8) * BATCH + b) * DMODEL + col) =
            make_float2(o[nj][2] * inv1, o[nj][3] * inv1);
    }
}

// ---------------- Router -------------------------------------------------------
__global__ void zero_cnt_kernel(int* cnt) { if (threadIdx.x < NEXP) cnt[threadIdx.x] = 0; }

__global__ __launch_bounds__(256) void router_kernel(
    const float* __restrict__ h, const float* __restrict__ gw,
    float* __restrict__ logits_out,
    int* __restrict__ rows, float* __restrict__ rwgt,
    int* __restrict__ trow, int* __restrict__ cnt)
{
    const int warp = threadIdx.x >> 5, lane = threadIdx.x & 31;
    const int t = blockIdx.x * 8 + warp;
    const float* hr = h + (size_t)t * DMODEL;
    float lg[NEXP];
    #pragma unroll
    for (int e = 0; e < NEXP; e++) {
        const float* gr = gw + e * DMODEL;
        float p = 0.f;
        for (int i = lane; i < DMODEL; i += 32) p += hr[i] * gr[i];
        #pragma unroll
        for (int off = 16; off; off >>= 1) p += __shfl_xor_sync(0xffffffffu, p, off);
        lg[e] = p;
    }
    if (lane == 0) {
        if (logits_out) {
            #pragma unroll
            for (int e = 0; e < NEXP; e++) logits_out[(size_t)t * NEXP + e] = lg[e];
        }
        float mx = lg[0];
        #pragma unroll
        for (int e = 1; e < NEXP; e++) mx = fmaxf(mx, lg[e]);
        float pr[NEXP];
        #pragma unroll
        for (int e = 0; e < NEXP; e++) pr[e] = __expf(lg[e] - mx);
        int i0 = 0;
        #pragma unroll
        for (int e = 1; e < NEXP; e++) if (pr[e] > pr[i0]) i0 = e;
        int i1 = (i0 == 0) ? 1 : 0;
        #pragma unroll
        for (int e = 0; e < NEXP; e++) if (e != i0 && pr[e] > pr[i1]) i1 = e;
        const float ws = pr[i0] + pr[i1];
        const float w0 = pr[i0] / ws, w1 = pr[i1] / ws;
        int p0 = atomicAdd(&cnt[i0], 1);
        rows[i0*NTOK + p0] = t; rwgt[i0*NTOK + p0] = w0; trow[2*t + 0] = i0*NTOK + p0;
        int p1 = atomicAdd(&cnt[i1], 1);
        rows[i1*NTOK + p1] = t; rwgt[i1*NTOK + p1] = w1; trow[2*t + 1] = i1*NTOK + p1;
    }
}

// ---------------- Final combine ------------------------------------------------
__global__ __launch_bounds__(256) void combine_kernel(
    const float* __restrict__ x2, const float* __restrict__ y,
    const int* __restrict__ trow, float* __restrict__ out)
{
    const int t = blockIdx.x;
    const int r0 = trow[2*t], r1 = trow[2*t + 1];
    const int i = threadIdx.x * 4;
    float4 a  = *(const float4*)(x2 + (size_t)t  * DMODEL + i);
    float4 y0 = *(const float4*)(y  + (size_t)r0 * DMODEL + i);
    float4 y1 = *(const float4*)(y  + (size_t)r1 * DMODEL + i);
    float4 o = make_float4(a.x + y0.x + y1.x, a.y + y0.y + y1.y,
                           a.z + y0.z + y1.z, a.w + y0.w + y1.w);
    *(float4*)(out + (size_t)t * DMODEL + i) = o;
}

// ---------------- host orchestration ------------------------------------------
extern "C" void kernel_launch(void* const* d_in, const int* in_sizes, int n_in,
                              void* d_out, int out_size)
{
    const float* x        = (const float*)d_in[0];
    const float* inproj_w = (const float*)d_in[1];
    const float* inproj_b = (const float*)d_in[2];
    const float* outproj_w= (const float*)d_in[3];
    const float* outproj_b= (const float*)d_in[4];
    const float* ln1_g    = (const float*)d_in[5];
    const float* ln1_b    = (const float*)d_in[6];
    const float* ln2_g    = (const float*)d_in[7];
    const float* ln2_b    = (const float*)d_in[8];
    const float* gate_w   = (const float*)d_in[9];
    const float* w1       = (const float*)d_in[10];
    const float* w2       = (const float*)d_in[11];
    const float* w3       = (const float*)d_in[12];

    float* out = (float*)d_out;
    float* logits_out = (out_size > NTOK * DMODEL) ? out + (size_t)NTOK * DMODEL : nullptr;

    float *p_ln1, *p_qkv, *p_attn, *p_x2, *p_ln2, *p_h1, *p_y, *p_rwgt;
    int *p_rows, *p_trow, *p_cnt;
    cudaGetSymbolAddress((void**)&p_ln1,  g_ln1);
    cudaGetSymbolAddress((void**)&p_qkv,  g_qkv);
    cudaGetSymbolAddress((void**)&p_attn, g_attn);
    cudaGetSymbolAddress((void**)&p_x2,   g_x2);
    cudaGetSymbolAddress((void**)&p_ln2,  g_ln2);
    cudaGetSymbolAddress((void**)&p_h1,   g_h1);
    cudaGetSymbolAddress((void**)&p_y,    g_y);
    cudaGetSymbolAddress((void**)&p_rwgt, g_rwgt);
    cudaGetSymbolAddress((void**)&p_rows, g_rows);
    cudaGetSymbolAddress((void**)&p_trow, g_trow);
    cudaGetSymbolAddress((void**)&p_cnt,  g_cnt);

    cudaFuncSetAttribute(gemm_tf32<1,false,false>, cudaFuncAttributeMaxDynamicSharedMemorySize, GEMM_SMEM);
    cudaFuncSetAttribute(gemm_tf32<2,false,false>, cudaFuncAttributeMaxDynamicSharedMemorySize, GEMM_SMEM);
    cudaFuncSetAttribute(gemm_tf32<0,true, true >, cudaFuncAttributeMaxDynamicSharedMemorySize, GEMM_SMEM);
    cudaFuncSetAttribute(gemm_tf32<3,true, true >, cudaFuncAttributeMaxDynamicSharedMemorySize, GEMM_SMEM);
    cudaFuncSetAttribute(gemm_tf32<4,false,true >, cudaFuncAttributeMaxDynamicSharedMemorySize, GEMM_SMEM);
    cudaFuncSetAttribute(flash_attn_mma,           cudaFuncAttributeMaxDynamicSharedMemorySize, FA2_SMEM);

    // 1. LN1
    ln_kernel<<<NTOK, 256>>>(x, ln1_g, ln1_b, p_ln1);

    // 2. QKV = ln1 @ W_in^T + b   [4096, 3072]
    gemm_tf32<1,false,false><<<dim3(3*DMODEL/128, NTOK/128), 256, GEMM_SMEM>>>(
        p_ln1, inproj_w, p_qkv, inproj_b, nullptr, nullptr, nullptr, nullptr, nullptr,
        NTOK, 3*DMODEL, DMODEL, 0, 0, 0);

    // 3. Flash attention (tensor cores)
    flash_attn_mma<<<dim3(S_LEN/128, BATCH*NHEAD), 256, FA2_SMEM>>>(p_qkv, p_attn);

    // 4. x2 = x + attn @ W_out^T + b
    gemm_tf32<2,false,false><<<dim3(DMODEL/128, NTOK/128), 256, GEMM_SMEM>>>(
        p_attn, outproj_w, p_x2, outproj_b, x, nullptr, nullptr, nullptr, nullptr,
        NTOK, DMODEL, DMODEL, 0, 0, 0);

    // 5. LN2
    ln_kernel<<<NTOK, 256>>>(p_x2, ln2_g, ln2_b, p_ln2);

    // 6. Router
    zero_cnt_kernel<<<1, 32>>>(p_cnt);
    router_kernel<<<NTOK/8, 256>>>(p_ln2, gate_w, logits_out,
                                   p_rows, p_rwgt, p_trow, p_cnt);

    // 7. MoE expert GEMMs (grouped, gathered)
    gemm_tf32<0,true,true><<<dim3(FFN_DIM/128, NTOK/128, NEXP), 256, GEMM_SMEM>>>(
        p_ln2, w1, p_h1, nullptr, nullptr, nullptr, nullptr, p_rows, p_cnt,
        NTOK, FFN_DIM, DMODEL,
        0, (size_t)FFN_DIM*DMODEL, (size_t)NTOK*FFN_DIM);
    gemm_tf32<3,true,true><<<dim3(FFN_DIM/128, NTOK/128, NEXP), 256, GEMM_SMEM>>>(
        p_ln2, w3, p_h1, nullptr, nullptr, p_h1, nullptr, p_rows, p_cnt,
        NTOK, FFN_DIM, DMODEL,
        0, (size_t)FFN_DIM*DMODEL, (size_t)NTOK*FFN_DIM);
    gemm_tf32<4,false,true><<<dim3(DMODEL/128, NTOK/128, NEXP), 256, GEMM_SMEM>>>(
        p_h1, w2, p_y, nullptr, nullptr, nullptr, p_rwgt, nullptr, p_cnt,
        NTOK, DMODEL, FFN_DIM,
        (size_t)NTOK*FFN_DIM, (size_t)DMODEL*FFN_DIM, (size_t)NTOK*DMODEL);

    // 8. out = x2 + Y[slot0] + Y[slot1]
    combine_kernel<<<NTOK, 256>>>(p_x2, p_y, p_trow, out);
}